// round 3
// baseline (speedup 1.0000x reference)
#include <cuda_runtime.h>
#include <cstdint>

#define BATCH 256
#define NNODE 79
#define RAWF 26
#define DOUT 64
#define HID 256
#define NEDGE 3000
#define KP1 100                 // 97 inputs padded to 100
#define NROWS (BATCH*NNODE)     // 20224
#define TR 32                   // rows per MLP CTA
#define NCH 24
#define CH 125
#define NCELL (NNODE*NCH)

// ---------------- device scratch ----------------
__device__ int   g_srcp[NEDGE];
__device__ int   g_dstp[NEDGE];
__device__ float g_ewp[NEDGE];
__device__ int   g_rowptr[NNODE + 1];
__device__ float g_W1T[KP1 * HID];
__device__ float g_W2T[HID * HID];
__device__ float g_hin[(size_t)NROWS * KP1];
__device__ float g_conc[NROWS];

__device__ __forceinline__ float wredsum(float v) {
    #pragma unroll
    for (int o = 16; o; o >>= 1) v += __shfl_xor_sync(0xffffffffu, v, o);
    return v;
}
__device__ __forceinline__ float wredmax(float v) {
    #pragma unroll
    for (int o = 16; o; o >>= 1) v = fmaxf(v, __shfl_xor_sync(0xffffffffu, v, o));
    return v;
}

// ---------------- setup: stable CSR sort of edges by dst ----------------
__global__ __launch_bounds__(256) void setup_kernel(const int* __restrict__ ei,
                                                    const float* __restrict__ ew) {
    __shared__ int dsts[NEDGE];
    __shared__ int cell[NCELL];
    __shared__ int wsum[8];
    int tid = threadIdx.x, lane = tid & 31, w = tid >> 5;
    for (int e = tid; e < NEDGE; e += 256) dsts[e] = ei[NEDGE + e];
    __syncthreads();
    for (int c = tid; c < NCELL; c += 256) {
        int b = c / NCH, ch = c - b * NCH, s = ch * CH, cnt = 0;
        for (int e = s; e < s + CH; e++) cnt += (dsts[e] == b);
        cell[c] = cnt;
    }
    __syncthreads();
    // exclusive scan over NCELL entries: 8 per thread + warp scan + cross-warp
    int base = tid * 8, loc[8], s = 0;
    #pragma unroll
    for (int j = 0; j < 8; j++) {
        int v = (base + j < NCELL) ? cell[base + j] : 0;
        loc[j] = s; s += v;
    }
    int x = s;
    #pragma unroll
    for (int o = 1; o < 32; o <<= 1) {
        int t = __shfl_up_sync(0xffffffffu, x, o);
        if (lane >= o) x += t;
    }
    if (lane == 31) wsum[w] = x;
    int exw = x - s;
    __syncthreads();
    if (tid == 0) {
        int a = 0;
        for (int i = 0; i < 8; i++) { int t = wsum[i]; wsum[i] = a; a += t; }
    }
    __syncthreads();
    int off = wsum[w] + exw;
    #pragma unroll
    for (int j = 0; j < 8; j++) if (base + j < NCELL) cell[base + j] = off + loc[j];
    __syncthreads();
    if (tid < NNODE) g_rowptr[tid] = cell[tid * NCH];
    if (tid == 0) g_rowptr[NNODE] = NEDGE;
    for (int c = tid; c < NCELL; c += 256) {
        int b = c / NCH, ch = c - b * NCH, s0 = ch * CH, o = cell[c];
        for (int e = s0; e < s0 + CH; e++)
            if (dsts[e] == b) { g_dstp[o] = b; g_srcp[o] = ei[e]; g_ewp[o] = ew[e]; o++; }
    }
}

// ---------------- transpose W1,W2 to k-major (W1 zero-padded to KP1) ----------------
__global__ __launch_bounds__(256) void transpose_kernel(const float* __restrict__ W1,
                                                        const float* __restrict__ W2) {
    int gtid = blockIdx.x * 256 + threadIdx.x, gs = gridDim.x * 256;
    for (int t = gtid; t < KP1 * HID; t += gs) {
        int k = t >> 8, j = t & 255;
        g_W1T[t] = (k < 97) ? W1[j * 97 + k] : 0.f;
    }
    for (int t = gtid; t < HID * HID; t += gs) {
        int k = t >> 8, j = t & 255;
        g_W2T[t] = W2[j * HID + k];
    }
}

// ---------------- conv: one CTA per batch element ----------------
#define CONV_SMEM_FLOATS 34796
__global__ __launch_bounds__(256) void conv_kernel(
    const float* __restrict__ state, const float* __restrict__ pos,
    const float* __restrict__ Wq, const float* __restrict__ bq,
    const float* __restrict__ Wk, const float* __restrict__ bk,
    const float* __restrict__ Wv, const float* __restrict__ bv,
    const float* __restrict__ We,
    const float* __restrict__ Wsk, const float* __restrict__ bsk) {
    extern __shared__ float sm[];
    float* xs  = sm;            // 80*33 = 2640
    float* qs  = xs + 2640;     // 80*64 = 5120
    float* ks  = qs + 5120;
    float* vs  = ks + 5120;
    float* sk  = vs + 5120;
    float* alp = sk + 5120;     // 3000
    float* Wqs = alp + 3000;    // 64*33 = 2112
    float* Wks = Wqs + 2112;
    float* Wvs = Wks + 2112;
    float* Wss = Wvs + 2112;
    float* qWe = Wss + 2112;    // 80
    float* wes = qWe + 80;      // 64
    float* tot = wes + 64;      // 4
    int*   rps = (int*)(tot + 4); // 80

    int b = blockIdx.x, tid = threadIdx.x, lane = tid & 31, w = tid >> 5;

    for (int idx = tid; idx < 80 * 32; idx += 256) {
        int i = idx >> 5, k = idx & 31;
        float v = 0.f;
        if (i < NNODE) v = (k < RAWF) ? state[((size_t)b * NNODE + i) * RAWF + k]
                                      : pos[i * 6 + (k - RAWF)];
        xs[i * 33 + k] = v;
    }
    for (int idx = tid; idx < 64 * 32; idx += 256) {
        int d = idx >> 5, k = idx & 31;
        Wqs[d * 33 + k] = Wq[idx];
        Wks[d * 33 + k] = Wk[idx];
        Wvs[d * 33 + k] = Wv[idx];
        Wss[d * 33 + k] = Wsk[idx];
    }
    if (tid <= NNODE) rps[tid] = g_rowptr[tid];
    if (tid < 64) wes[tid] = We[tid];
    __syncthreads();

    if (tid == 0) {
        float t = 0.f;
        for (int i = 0; i < NNODE; i++) t += xs[i * 33 + 1];
        tot[0] = t;
    }

    // q,k,v,skip GEMMs: thread handles 1 channel x 4 nodes per item
    #pragma unroll 1
    for (int it = 0; it < 5; it++) {
        int item = tid + it * 256;
        int d = item & 63, i0 = (item >> 6) << 2;
        const float* wq = Wqs + d * 33; const float* wk = Wks + d * 33;
        const float* wv = Wvs + d * 33; const float* ws = Wss + d * 33;
        float aq[4] = {0,0,0,0}, ak[4] = {0,0,0,0}, av[4] = {0,0,0,0}, ap[4] = {0,0,0,0};
        #pragma unroll 4
        for (int k = 0; k < 32; k++) {
            float wqv = wq[k], wkv = wk[k], wvv = wv[k], wsv = ws[k];
            #pragma unroll
            for (int n = 0; n < 4; n++) {
                float xv = xs[(i0 + n) * 33 + k];
                aq[n] += xv * wqv; ak[n] += xv * wkv;
                av[n] += xv * wvv; ap[n] += xv * wsv;
            }
        }
        float bqv = bq[d], bkv = bk[d], bvv = bv[d], bsv = bsk[d];
        #pragma unroll
        for (int n = 0; n < 4; n++) {
            qs[(i0 + n) * 64 + d] = aq[n] + bqv;
            ks[(i0 + n) * 64 + d] = ak[n] + bkv;
            vs[(i0 + n) * 64 + d] = av[n] + bvv;
            sk[(i0 + n) * 64 + d] = ap[n] + bsv;
        }
    }
    __syncthreads();

    if (tid < NNODE) {
        float a = 0.f;
        const float* qr = qs + tid * 64;
        #pragma unroll 8
        for (int d = 0; d < 64; d++) a += qr[d] * wes[d];
        qWe[tid] = a;
    }
    __syncthreads();

    // alpha: 8-lane group per edge
    {
        int g = lane >> 3, li = lane & 7;
        for (int e = w * 4 + g; e < NEDGE; e += 32) {
            int dd = g_dstp[e], ss = g_srcp[e];
            float ewv = g_ewp[e];
            const float4* qr = (const float4*)(qs + dd * 64 + li * 8);
            const float4* kr = (const float4*)(ks + ss * 64 + li * 8);
            float4 q0 = qr[0], q1 = qr[1], k0 = kr[0], k1 = kr[1];
            float p = q0.x*k0.x + q0.y*k0.y + q0.z*k0.z + q0.w*k0.w
                    + q1.x*k1.x + q1.y*k1.y + q1.z*k1.z + q1.w*k1.w;
            p += __shfl_xor_sync(0xffffffffu, p, 1);
            p += __shfl_xor_sync(0xffffffffu, p, 2);
            p += __shfl_xor_sync(0xffffffffu, p, 4);
            if (li == 0) alp[e] = 0.125f * (p + ewv * qWe[dd]);
        }
    }
    __syncthreads();

    // softmax + aggregation: warp per node
    float we0 = wes[lane], we1 = wes[lane + 32];
    for (int i = w; i < NNODE; i += 8) {
        int s0 = rps[i], e1 = rps[i + 1];
        float a0 = 0.f, a1 = 0.f;
        if (e1 > s0) {
            float m = -1e30f;
            for (int e = s0 + lane; e < e1; e += 32) m = fmaxf(m, alp[e]);
            m = wredmax(m);
            float den = 0.f;
            for (int e = s0 + lane; e < e1; e += 32) {
                float ex = __expf(alp[e] - m);
                alp[e] = ex; den += ex;
            }
            den = wredsum(den);
            float inv = 1.f / (den + 1e-16f);
            float sew = 0.f;
            for (int e = s0; e < e1; e++) {
                float wg = alp[e] * inv;
                int ss = g_srcp[e];
                a0 += wg * vs[ss * 64 + lane];
                a1 += wg * vs[ss * 64 + lane + 32];
                sew += wg * g_ewp[e];
            }
            a0 += sew * we0; a1 += sew * we1;
        }
        size_t r = (size_t)b * NNODE + i;
        g_hin[r * KP1 + lane]      = fmaxf(a0 + sk[i * 64 + lane], 0.f);
        g_hin[r * KP1 + lane + 32] = fmaxf(a1 + sk[i * 64 + lane + 32], 0.f);
    }
    __syncthreads();

    // tail of hin rows: [64]=total, [65..96]=x, [97..99]=0
    for (int idx = tid; idx < NNODE * 36; idx += 256) {
        int i = idx / 36, c = idx - i * 36;
        size_t r = (size_t)b * NNODE + i;
        float v;
        if (c == 0) v = tot[0];
        else if (c <= 32) v = xs[i * 33 + (c - 1)];
        else v = 0.f;
        g_hin[r * KP1 + 64 + c] = v;
    }
}

// ---------------- fused MLP (GEMM+LN+lrelu x2 + head) ----------------
#define MLP_SMEM_FLOATS (TR*KP1 + TR*HID + TR + TR + HID)
__global__ __launch_bounds__(256) void mlp_kernel(
    const float* __restrict__ b1, const float* __restrict__ g1, const float* __restrict__ be1,
    const float* __restrict__ b2, const float* __restrict__ g2, const float* __restrict__ be2,
    const float* __restrict__ W3, const float* __restrict__ b3) {
    extern __shared__ float sm[];
    float* xs  = sm;                 // TR*KP1
    float* hb  = xs + TR * KP1;      // TR*HID
    float* mu  = hb + TR * HID;      // TR
    float* rsd = mu + TR;            // TR
    float* w3s = rsd + TR;           // HID
    int tid = threadIdx.x, lane = tid & 31, w = tid >> 5;
    size_t row0 = (size_t)blockIdx.x * TR;

    const float4* srcp = (const float4*)(g_hin + row0 * KP1);
    float4* dstp = (float4*)xs;
    for (int i = tid; i < TR * KP1 / 4; i += 256) dstp[i] = srcp[i];
    w3s[tid] = W3[tid];
    __syncthreads();

    float acc[TR];
    float bv = b1[tid];
    #pragma unroll
    for (int r = 0; r < TR; r++) acc[r] = bv;
    for (int kk = 0; kk < KP1; kk += 4) {
        float w0 = g_W1T[(kk + 0) * HID + tid], w1 = g_W1T[(kk + 1) * HID + tid];
        float w2 = g_W1T[(kk + 2) * HID + tid], w3 = g_W1T[(kk + 3) * HID + tid];
        #pragma unroll
        for (int r = 0; r < TR; r++) {
            float4 xv = *(const float4*)(xs + r * KP1 + kk);
            acc[r] += xv.x * w0 + xv.y * w1 + xv.z * w2 + xv.w * w3;
        }
    }
    #pragma unroll
    for (int r = 0; r < TR; r++) hb[r * HID + tid] = acc[r];
    __syncthreads();
    for (int i = w; i < TR; i += 8) {
        float s = 0.f, s2 = 0.f;
        #pragma unroll
        for (int t = 0; t < 8; t++) { float v = hb[i * HID + lane + t * 32]; s += v; s2 += v * v; }
        s = wredsum(s); s2 = wredsum(s2);
        if (lane == 0) {
            float m = s * (1.f / HID);
            mu[i] = m;
            rsd[i] = rsqrtf(s2 * (1.f / HID) - m * m + 1e-5f);
        }
    }
    __syncthreads();
    {
        float gv = g1[tid], bev = be1[tid];
        #pragma unroll
        for (int r = 0; r < TR; r++) {
            float h = (acc[r] - mu[r]) * rsd[r] * gv + bev;
            hb[r * HID + tid] = h > 0.f ? h : 0.01f * h;
        }
    }
    __syncthreads();

    float bv2 = b2[tid];
    #pragma unroll
    for (int r = 0; r < TR; r++) acc[r] = bv2;
    for (int kk = 0; kk < HID; kk += 4) {
        float w0 = g_W2T[(kk + 0) * HID + tid], w1 = g_W2T[(kk + 1) * HID + tid];
        float w2 = g_W2T[(kk + 2) * HID + tid], w3 = g_W2T[(kk + 3) * HID + tid];
        #pragma unroll
        for (int r = 0; r < TR; r++) {
            float4 xv = *(const float4*)(hb + r * HID + kk);
            acc[r] += xv.x * w0 + xv.y * w1 + xv.z * w2 + xv.w * w3;
        }
    }
    __syncthreads();
    #pragma unroll
    for (int r = 0; r < TR; r++) hb[r * HID + tid] = acc[r];
    __syncthreads();
    for (int i = w; i < TR; i += 8) {
        float s = 0.f, s2 = 0.f;
        #pragma unroll
        for (int t = 0; t < 8; t++) { float v = hb[i * HID + lane + t * 32]; s += v; s2 += v * v; }
        s = wredsum(s); s2 = wredsum(s2);
        if (lane == 0) {
            float m = s * (1.f / HID);
            mu[i] = m;
            rsd[i] = rsqrtf(s2 * (1.f / HID) - m * m + 1e-5f);
        }
    }
    __syncthreads();
    {
        float gv = g2[tid], bev = be2[tid], w3v = w3s[tid];
        #pragma unroll
        for (int r = 0; r < TR; r++) {
            float h = (acc[r] - mu[r]) * rsd[r] * gv + bev;
            h = h > 0.f ? h : 0.01f * h;
            hb[r * HID + tid] = h * w3v;
        }
    }
    __syncthreads();
    float b3v = b3[0];
    for (int i = w; i < TR; i += 8) {
        float s = 0.f;
        #pragma unroll
        for (int t = 0; t < 8; t++) s += hb[i * HID + lane + t * 32];
        s = wredsum(s);
        if (lane == 0) {
            float yv = s + b3v;
            g_conc[row0 + i] = (yv > 20.f) ? yv : log1pf(expf(yv));
        }
    }
}

// ---------------- final normalize per batch ----------------
__global__ __launch_bounds__(128) void final_kernel(float* __restrict__ out) {
    __shared__ float sb[4];
    int b = blockIdx.x, tid = threadIdx.x, lane = tid & 31, w = tid >> 5;
    float v = (tid < NNODE) ? g_conc[b * NNODE + tid] : 0.f;
    float s = v;
    #pragma unroll
    for (int o = 16; o; o >>= 1) s += __shfl_xor_sync(0xffffffffu, s, o);
    if (lane == 0) sb[w] = s;
    __syncthreads();
    float tot = sb[0] + sb[1] + sb[2] + sb[3];
    if (tid < NNODE) out[b * NNODE + tid] = v / (tot + 1e-20f);
}

// ---------------- launch ----------------
extern "C" void kernel_launch(void* const* d_in, const int* in_sizes, int n_in,
                              void* d_out, int out_size) {
    const float* state = (const float*)d_in[0];
    const float* pos   = (const float*)d_in[1];
    const float* ew    = (const float*)d_in[2];
    const float* Wq  = (const float*)d_in[3];  const float* bq  = (const float*)d_in[4];
    const float* Wk  = (const float*)d_in[5];  const float* bk  = (const float*)d_in[6];
    const float* Wv  = (const float*)d_in[7];  const float* bv  = (const float*)d_in[8];
    const float* We  = (const float*)d_in[9];
    const float* Wsk = (const float*)d_in[10]; const float* bsk = (const float*)d_in[11];
    const float* W1  = (const float*)d_in[12]; const float* b1  = (const float*)d_in[13];
    const float* g1  = (const float*)d_in[14]; const float* be1 = (const float*)d_in[15];
    const float* W2  = (const float*)d_in[16]; const float* b2  = (const float*)d_in[17];
    const float* g2  = (const float*)d_in[18]; const float* be2 = (const float*)d_in[19];
    const float* W3  = (const float*)d_in[20]; const float* b3  = (const float*)d_in[21];
    const int*   ei  = (const int*)d_in[22];
    float* out = (float*)d_out;

    int conv_smem = CONV_SMEM_FLOATS * 4;
    int mlp_smem  = MLP_SMEM_FLOATS * 4;
    cudaFuncSetAttribute(conv_kernel, cudaFuncAttributeMaxDynamicSharedMemorySize, conv_smem);
    cudaFuncSetAttribute(mlp_kernel,  cudaFuncAttributeMaxDynamicSharedMemorySize, mlp_smem);

    setup_kernel<<<1, 256>>>(ei, ew);
    transpose_kernel<<<178, 256>>>(W1, W2);
    conv_kernel<<<BATCH, 256, conv_smem>>>(state, pos, Wq, bq, Wk, bk, Wv, bv, We, Wsk, bsk);
    mlp_kernel<<<NROWS / TR, 256, mlp_smem>>>(b1, g1, be1, b2, g2, be2, W3, b3);
    final_kernel<<<BATCH, 128>>>(out);
}

// round 4
// speedup vs baseline: 1.1483x; 1.1483x over previous
#include <cuda_runtime.h>
#include <cstdint>

typedef unsigned long long ull;

#define BATCH 256
#define NNODE 79
#define HID 256
#define NEDGE 3000
#define KP1 100
#define NROWS (BATCH*NNODE)     // 20224
#define NCH 24
#define CHSZ 125
#define NCELL (NNODE*NCH)       // 1896

// ---------------- device scratch ----------------
__device__ int   g_srcp[NEDGE];
__device__ int   g_dstp[NEDGE];
__device__ float g_ewp[NEDGE];
__device__ int   g_rowptr[NNODE + 1];
__device__ float g_W1D[KP1 * HID * 2];   // k-major, each value duplicated (f32x2)
__device__ float g_W2D[HID * HID * 2];
__device__ float g_hin[(size_t)NROWS * KP1];
__device__ float g_conc[NROWS];

__device__ __forceinline__ float wredsum(float v) {
    #pragma unroll
    for (int o = 16; o; o >>= 1) v += __shfl_xor_sync(0xffffffffu, v, o);
    return v;
}
__device__ __forceinline__ float wredmax(float v) {
    #pragma unroll
    for (int o = 16; o; o >>= 1) v = fmaxf(v, __shfl_xor_sync(0xffffffffu, v, o));
    return v;
}

// ---- packed fp32x2 helpers ----
__device__ __forceinline__ ull dup2(float v) {
    ull r; asm("mov.b64 %0,{%1,%1};" : "=l"(r) : "f"(v)); return r;
}
__device__ __forceinline__ ull pk2(float a, float b) {
    ull r; asm("mov.b64 %0,{%1,%2};" : "=l"(r) : "f"(a), "f"(b)); return r;
}
__device__ __forceinline__ ull f2fma(ull a, ull b, ull c) {
    ull d; asm("fma.rn.f32x2 %0,%1,%2,%3;" : "=l"(d) : "l"(a), "l"(b), "l"(c)); return d;
}
__device__ __forceinline__ void up2(ull v, float& lo, float& hi) {
    asm("mov.b64 {%0,%1},%2;" : "=f"(lo), "=f"(hi) : "l"(v));
}

// ---------------- prep: block0 = CSR sort; blocks 1.. = weight transpose+dup ----------------
__global__ __launch_bounds__(256) void prep_kernel(const int* __restrict__ ei,
                                                   const float* __restrict__ ew,
                                                   const float* __restrict__ W1,
                                                   const float* __restrict__ W2) {
    int tid = threadIdx.x;
    if (blockIdx.x == 0) {
        __shared__ int dsts[NEDGE];
        __shared__ int cell[NCELL];
        __shared__ int wsum[8];
        int lane = tid & 31, w = tid >> 5;
        for (int e = tid; e < NEDGE; e += 256) dsts[e] = ei[NEDGE + e];
        for (int c = tid; c < NCELL; c += 256) cell[c] = 0;
        __syncthreads();
        for (int e = tid; e < NEDGE; e += 256)
            atomicAdd(&cell[dsts[e] * NCH + e / CHSZ], 1);   // int atomics: deterministic
        __syncthreads();
        // exclusive scan over NCELL: 8/thread + warp scan + cross-warp
        int base = tid * 8, loc[8], s = 0;
        #pragma unroll
        for (int j = 0; j < 8; j++) {
            int v = (base + j < NCELL) ? cell[base + j] : 0;
            loc[j] = s; s += v;
        }
        int x = s;
        #pragma unroll
        for (int o = 1; o < 32; o <<= 1) {
            int t = __shfl_up_sync(0xffffffffu, x, o);
            if (lane >= o) x += t;
        }
        if (lane == 31) wsum[w] = x;
        int exw = x - s;
        __syncthreads();
        if (tid == 0) {
            int a = 0;
            for (int i = 0; i < 8; i++) { int t = wsum[i]; wsum[i] = a; a += t; }
        }
        __syncthreads();
        int off = wsum[w] + exw;
        #pragma unroll
        for (int j = 0; j < 8; j++) if (base + j < NCELL) cell[base + j] = off + loc[j];
        __syncthreads();
        if (tid < NNODE) g_rowptr[tid] = cell[tid * NCH];
        if (tid == 0) g_rowptr[NNODE] = NEDGE;
        // scatter: rank within (chunk, dst) by in-chunk scan -> stable & parallel
        for (int e = tid; e < NEDGE; e += 256) {
            int d = dsts[e];
            int ch = e / CHSZ, b0 = ch * CHSZ;
            int rank = 0;
            for (int e2 = b0; e2 < e; e2++) rank += (dsts[e2] == d);
            int pos = cell[d * NCH + ch] + rank;
            g_dstp[pos] = d; g_srcp[pos] = ei[e]; g_ewp[pos] = ew[e];
        }
    } else {
        int gtid = (blockIdx.x - 1) * 256 + tid, gs = (gridDim.x - 1) * 256;
        for (int t = gtid; t < KP1 * HID; t += gs) {
            int k = t >> 8, j = t & 255;
            float v = (k < 97) ? W1[j * 97 + k] : 0.f;
            g_W1D[t * 2] = v; g_W1D[t * 2 + 1] = v;
        }
        for (int t = gtid; t < HID * HID; t += gs) {
            int k = t >> 8, j = t & 255;
            float v = W2[j * HID + k];
            g_W2D[t * 2] = v; g_W2D[t * 2 + 1] = v;
        }
    }
}

// ---------------- conv: one CTA per batch; 2 CTAs/SM ----------------
// smem floats: xs 2640 | WA 2080 | WB 2080 | qs/ks/vs 3*5056 | alp 3000 | qWe 80 | wes 64 | tot 4 | rps 80
#define CONV_SMEM_FLOATS (2640 + 2*2080 + 3*5056 + 3000 + 80 + 64 + 4 + 80)
#define CONV_SMEM_BYTES  (CONV_SMEM_FLOATS * 4)

__global__ __launch_bounds__(256) void conv_kernel(
    const float* __restrict__ state, const float* __restrict__ pos,
    const float* __restrict__ Wq, const float* __restrict__ bq,
    const float* __restrict__ Wk, const float* __restrict__ bk,
    const float* __restrict__ Wv, const float* __restrict__ bv,
    const float* __restrict__ We,
    const float* __restrict__ Wsk, const float* __restrict__ bsk) {
    extern __shared__ float sm[];
    float* xs  = sm;              // 80*33
    float* WA  = xs + 2640;       // 32*65 k-major
    float* WB  = WA + 2080;
    float* qs  = WB + 2080;       // 79*64
    float* ks  = qs + 5056;
    float* vs  = ks + 5056;
    float* alp = vs + 5056;       // 3000
    float* qWe = alp + 3000;      // 80
    float* wes = qWe + 80;        // 64
    float* tot = wes + 64;        // 4
    int*   rps = (int*)(tot + 4); // 80

    int b = blockIdx.x, tid = threadIdx.x, lane = tid & 31, w = tid >> 5;

    // phase 1: load x (row 79 zero), stage Wq,Wk k-major (pad 65)
    for (int idx = tid; idx < 80 * 32; idx += 256) {
        int i = idx >> 5, k = idx & 31;
        float v = 0.f;
        if (i < NNODE) v = (k < 26) ? state[((size_t)b * NNODE + i) * 26 + k]
                                    : pos[i * 6 + (k - 26)];
        xs[i * 33 + k] = v;
    }
    for (int idx = tid; idx < 64 * 32; idx += 256) {
        int d = idx >> 5, k = idx & 31;
        WA[k * 65 + d] = Wq[idx];
        WB[k * 65 + d] = Wk[idx];
    }
    if (tid <= NNODE) rps[tid] = g_rowptr[tid];
    if (tid < 64) wes[tid] = We[tid];
    __syncthreads();

    // phase 2: total agents + GEMM A (q,k)
    if (tid == 0) {
        float t = 0.f;
        for (int i = 0; i < NNODE; i++) t += xs[i * 33 + 1];
        tot[0] = t;
    }
    #pragma unroll 1
    for (int it = 0; it < 5; it++) {
        int item = tid + it * 256;
        int d = item & 63, i0 = (item >> 6) << 2;
        float aq[4] = {0,0,0,0}, ak[4] = {0,0,0,0};
        #pragma unroll 8
        for (int k = 0; k < 32; k++) {
            float wq = WA[k * 65 + d], wk = WB[k * 65 + d];
            #pragma unroll
            for (int n = 0; n < 4; n++) {
                float xv = xs[(i0 + n) * 33 + k];
                aq[n] += xv * wq; ak[n] += xv * wk;
            }
        }
        float bqv = __ldg(bq + d), bkv = __ldg(bk + d);
        #pragma unroll
        for (int n = 0; n < 4; n++) {
            if (i0 + n < NNODE) {
                qs[(i0 + n) * 64 + d] = aq[n] + bqv;
                ks[(i0 + n) * 64 + d] = ak[n] + bkv;
            }
        }
    }
    __syncthreads();

    // phase 3a: qWe, tail of hin, restage Wv,Wsk
    if (tid < NNODE) {
        float a = 0.f;
        const float* qr = qs + tid * 64;
        #pragma unroll 8
        for (int d = 0; d < 64; d++) a += qr[d] * wes[d];
        qWe[tid] = a;
    }
    for (int idx = tid; idx < 64 * 32; idx += 256) {
        int d = idx >> 5, k = idx & 31;
        WA[k * 65 + d] = Wv[idx];
        WB[k * 65 + d] = Wsk[idx];
    }
    for (int idx = tid; idx < NNODE * 36; idx += 256) {
        int i = idx / 36, c = idx - i * 36;
        size_t r = (size_t)b * NNODE + i;
        float v;
        if (c == 0) v = tot[0];
        else if (c <= 32) v = xs[i * 33 + (c - 1)];
        else v = 0.f;
        g_hin[r * KP1 + 64 + c] = v;
    }
    __syncthreads();

    // phase 3b: GEMM B (v, skip->g_hin raw) + alpha
    #pragma unroll 1
    for (int it = 0; it < 5; it++) {
        int item = tid + it * 256;
        int d = item & 63, i0 = (item >> 6) << 2;
        float av[4] = {0,0,0,0}, as[4] = {0,0,0,0};
        #pragma unroll 8
        for (int k = 0; k < 32; k++) {
            float wv = WA[k * 65 + d], ws = WB[k * 65 + d];
            #pragma unroll
            for (int n = 0; n < 4; n++) {
                float xv = xs[(i0 + n) * 33 + k];
                av[n] += xv * wv; as[n] += xv * ws;
            }
        }
        float bvv = __ldg(bv + d), bsv = __ldg(bsk + d);
        #pragma unroll
        for (int n = 0; n < 4; n++) {
            if (i0 + n < NNODE) {
                vs[(i0 + n) * 64 + d] = av[n] + bvv;
                g_hin[((size_t)b * NNODE + i0 + n) * KP1 + d] = as[n] + bsv;
            }
        }
    }
    {
        int g = lane >> 3, li = lane & 7;
        for (int e = w * 4 + g; e < NEDGE; e += 32) {
            int dd = g_dstp[e], ss = g_srcp[e];
            float ewv = g_ewp[e];
            const float4* qr = (const float4*)(qs + dd * 64 + li * 8);
            const float4* kr = (const float4*)(ks + ss * 64 + li * 8);
            float4 q0 = qr[0], q1 = qr[1], k0 = kr[0], k1 = kr[1];
            float p = q0.x*k0.x + q0.y*k0.y + q0.z*k0.z + q0.w*k0.w
                    + q1.x*k1.x + q1.y*k1.y + q1.z*k1.z + q1.w*k1.w;
            p += __shfl_xor_sync(0xffffffffu, p, 1);
            p += __shfl_xor_sync(0xffffffffu, p, 2);
            p += __shfl_xor_sync(0xffffffffu, p, 4);
            if (li == 0) alp[e] = 0.125f * (p + ewv * qWe[dd]);
        }
    }
    __syncthreads();

    // phase 4: softmax + aggregation (warp per node), add skip, relu -> g_hin
    float we0 = wes[lane], we1 = wes[lane + 32];
    for (int i = w; i < NNODE; i += 8) {
        int s0 = rps[i], e1 = rps[i + 1];
        float a0 = 0.f, a1 = 0.f;
        if (e1 > s0) {
            float m = -1e30f;
            for (int e = s0 + lane; e < e1; e += 32) m = fmaxf(m, alp[e]);
            m = wredmax(m);
            float den = 0.f;
            for (int e = s0 + lane; e < e1; e += 32) {
                float ex = __expf(alp[e] - m);
                alp[e] = ex; den += ex;
            }
            den = wredsum(den);
            float inv = 1.f / (den + 1e-16f);
            float sew = 0.f;
            for (int e = s0; e < e1; e++) {
                float wg = alp[e] * inv;
                int ss = g_srcp[e];
                a0 += wg * vs[ss * 64 + lane];
                a1 += wg * vs[ss * 64 + lane + 32];
                sew += wg * g_ewp[e];
            }
            a0 += sew * we0; a1 += sew * we1;
        }
        size_t r = (size_t)b * NNODE + i;
        float s0v = g_hin[r * KP1 + lane];
        float s1v = g_hin[r * KP1 + lane + 32];
        g_hin[r * KP1 + lane]      = fmaxf(a0 + s0v, 0.f);
        g_hin[r * KP1 + lane + 32] = fmaxf(a1 + s1v, 0.f);
    }
}

// ---------------- MLP: f32x2 packed, 64 rows/CTA ----------------
// smem floats: xs 6400 (32 pairs x 100 x 2) | hb 16384 (32 x 256 x 2) | mu 64 | rsd 64 | w3 256
#define MLP_SMEM_FLOATS (6400 + 16384 + 64 + 64 + 256)
#define MLP_SMEM_BYTES  (MLP_SMEM_FLOATS * 4)

__device__ __forceinline__ void gemm_f32x2(const float* __restrict__ WD,
                                           const float* __restrict__ xsrc, int K,
                                           float4 bvv, ull (&acc)[4][8],
                                           int c4, int pbase) {
    #pragma unroll
    for (int rp = 0; rp < 8; rp++) {
        acc[0][rp] = dup2(bvv.x); acc[1][rp] = dup2(bvv.y);
        acc[2][rp] = dup2(bvv.z); acc[3][rp] = dup2(bvv.w);
    }
    #pragma unroll 2
    for (int kk = 0; kk < K; kk += 2) {
        const ulonglong2* w0 = (const ulonglong2*)(WD + (size_t)(kk * HID + 4 * c4) * 2);
        const ulonglong2* w1 = (const ulonglong2*)(WD + (size_t)((kk + 1) * HID + 4 * c4) * 2);
        ulonglong2 a0 = w0[0], a1 = w0[1], b0 = w1[0], b1 = w1[1];
        #pragma unroll
        for (int rp = 0; rp < 8; rp++) {
            ulonglong2 xv = *(const ulonglong2*)(xsrc + (size_t)((pbase + rp) * K + kk) * 2);
            acc[0][rp] = f2fma(xv.x, a0.x, acc[0][rp]);
            acc[1][rp] = f2fma(xv.x, a0.y, acc[1][rp]);
            acc[2][rp] = f2fma(xv.x, a1.x, acc[2][rp]);
            acc[3][rp] = f2fma(xv.x, a1.y, acc[3][rp]);
            acc[0][rp] = f2fma(xv.y, b0.x, acc[0][rp]);
            acc[1][rp] = f2fma(xv.y, b0.y, acc[1][rp]);
            acc[2][rp] = f2fma(xv.y, b1.x, acc[2][rp]);
            acc[3][rp] = f2fma(xv.y, b1.y, acc[3][rp]);
        }
    }
}

__global__ __launch_bounds__(256) void mlp_kernel(
    const float* __restrict__ b1, const float* __restrict__ g1, const float* __restrict__ be1,
    const float* __restrict__ b2, const float* __restrict__ g2, const float* __restrict__ be2,
    const float* __restrict__ W3, const float* __restrict__ b3) {
    extern __shared__ float sm[];
    float* xs  = sm;                 // pair-interleaved x
    float* hb  = xs + 6400;          // pair-interleaved hidden
    float* mu  = hb + 16384;
    float* rsd = mu + 64;
    float* w3s = rsd + 64;
    ull* hbp = (ull*)hb;
    int tid = threadIdx.x, lane = tid & 31, w = tid >> 5;
    int c4 = tid & 63, rg = tid >> 6, pbase = rg * 8;
    size_t row0 = (size_t)blockIdx.x * 64;

    // load x pair-interleaved
    for (int idx = tid; idx < 64 * KP1; idx += 256) {
        int row = idx / KP1, k = idx - row * KP1;
        xs[((row >> 1) * KP1 + k) * 2 + (row & 1)] = g_hin[row0 * KP1 + idx];
    }
    w3s[tid] = W3[tid];
    __syncthreads();

    ull acc[4][8];
    // ---- layer 1 ----
    gemm_f32x2(g_W1D, xs, KP1, ((const float4*)b1)[c4], acc, c4, pbase);
    #pragma unroll
    for (int rp = 0; rp < 8; rp++)
        #pragma unroll
        for (int c = 0; c < 4; c++)
            hbp[(size_t)(pbase + rp) * HID + 4 * c4 + c] = acc[c][rp];
    __syncthreads();
    for (int r = w; r < 64; r += 8) {
        int pr = r >> 1, par = r & 1;
        float s = 0.f, s2 = 0.f;
        #pragma unroll
        for (int t = 0; t < 8; t++) {
            float v = hb[((size_t)pr * HID + lane + t * 32) * 2 + par];
            s += v; s2 += v * v;
        }
        s = wredsum(s); s2 = wredsum(s2);
        if (lane == 0) {
            float m = s * (1.f / HID);
            mu[r] = m;
            rsd[r] = rsqrtf(s2 * (1.f / HID) - m * m + 1e-5f);
        }
    }
    __syncthreads();
    {
        float4 gv = ((const float4*)g1)[c4], bev = ((const float4*)be1)[c4];
        float ga[4] = {gv.x, gv.y, gv.z, gv.w}, ba[4] = {bev.x, bev.y, bev.z, bev.w};
        #pragma unroll
        for (int rp = 0; rp < 8; rp++) {
            int pr = pbase + rp;
            float m0 = mu[2*pr], m1 = mu[2*pr+1], r0 = rsd[2*pr], r1 = rsd[2*pr+1];
            #pragma unroll
            for (int c = 0; c < 4; c++) {
                float lo, hi; up2(acc[c][rp], lo, hi);
                float h0 = (lo - m0) * r0 * ga[c] + ba[c];
                float h1 = (hi - m1) * r1 * ga[c] + ba[c];
                h0 = h0 > 0.f ? h0 : 0.01f * h0;
                h1 = h1 > 0.f ? h1 : 0.01f * h1;
                hbp[(size_t)pr * HID + 4 * c4 + c] = pk2(h0, h1);
            }
        }
    }
    __syncthreads();

    // ---- layer 2 ----
    gemm_f32x2(g_W2D, hb, HID, ((const float4*)b2)[c4], acc, c4, pbase);
    __syncthreads();   // all reads of hb done before overwrite
    #pragma unroll
    for (int rp = 0; rp < 8; rp++)
        #pragma unroll
        for (int c = 0; c < 4; c++)
            hbp[(size_t)(pbase + rp) * HID + 4 * c4 + c] = acc[c][rp];
    __syncthreads();
    for (int r = w; r < 64; r += 8) {
        int pr = r >> 1, par = r & 1;
        float s = 0.f, s2 = 0.f;
        #pragma unroll
        for (int t = 0; t < 8; t++) {
            float v = hb[((size_t)pr * HID + lane + t * 32) * 2 + par];
            s += v; s2 += v * v;
        }
        s = wredsum(s); s2 = wredsum(s2);
        if (lane == 0) {
            float m = s * (1.f / HID);
            mu[r] = m;
            rsd[r] = rsqrtf(s2 * (1.f / HID) - m * m + 1e-5f);
        }
    }
    __syncthreads();
    {
        float4 gv = ((const float4*)g2)[c4], bev = ((const float4*)be2)[c4];
        float ga[4] = {gv.x, gv.y, gv.z, gv.w}, ba[4] = {bev.x, bev.y, bev.z, bev.w};
        #pragma unroll
        for (int rp = 0; rp < 8; rp++) {
            int pr = pbase + rp;
            float m0 = mu[2*pr], m1 = mu[2*pr+1], r0 = rsd[2*pr], r1 = rsd[2*pr+1];
            #pragma unroll
            for (int c = 0; c < 4; c++) {
                float lo, hi; up2(acc[c][rp], lo, hi);
                float w3c = w3s[4 * c4 + c];
                float h0 = (lo - m0) * r0 * ga[c] + ba[c];
                float h1 = (hi - m1) * r1 * ga[c] + ba[c];
                h0 = h0 > 0.f ? h0 : 0.01f * h0;
                h1 = h1 > 0.f ? h1 : 0.01f * h1;
                hbp[(size_t)pr * HID + 4 * c4 + c] = pk2(h0 * w3c, h1 * w3c);
            }
        }
    }
    __syncthreads();
    float b3v = b3[0];
    for (int r = w; r < 64; r += 8) {
        int pr = r >> 1, par = r & 1;
        float s = 0.f;
        #pragma unroll
        for (int t = 0; t < 8; t++)
            s += hb[((size_t)pr * HID + lane + t * 32) * 2 + par];
        s = wredsum(s);
        if (lane == 0) {
            float yv = s + b3v;
            g_conc[row0 + r] = (yv > 20.f) ? yv : log1pf(expf(yv));
        }
    }
}

// ---------------- final normalize per batch ----------------
__global__ __launch_bounds__(128) void final_kernel(float* __restrict__ out) {
    __shared__ float sb[4];
    int b = blockIdx.x, tid = threadIdx.x, lane = tid & 31, w = tid >> 5;
    float v = (tid < NNODE) ? g_conc[b * NNODE + tid] : 0.f;
    float s = v;
    #pragma unroll
    for (int o = 16; o; o >>= 1) s += __shfl_xor_sync(0xffffffffu, s, o);
    if (lane == 0) sb[w] = s;
    __syncthreads();
    float tt = sb[0] + sb[1] + sb[2] + sb[3];
    if (tid < NNODE) out[b * NNODE + tid] = v / (tt + 1e-20f);
}

// ---------------- launch ----------------
extern "C" void kernel_launch(void* const* d_in, const int* in_sizes, int n_in,
                              void* d_out, int out_size) {
    const float* state = (const float*)d_in[0];
    const float* pos   = (const float*)d_in[1];
    const float* ew    = (const float*)d_in[2];
    const float* Wq  = (const float*)d_in[3];  const float* bq  = (const float*)d_in[4];
    const float* Wk  = (const float*)d_in[5];  const float* bk  = (const float*)d_in[6];
    const float* Wv  = (const float*)d_in[7];  const float* bv  = (const float*)d_in[8];
    const float* We  = (const float*)d_in[9];
    const float* Wsk = (const float*)d_in[10]; const float* bsk = (const float*)d_in[11];
    const float* W1  = (const float*)d_in[12]; const float* b1  = (const float*)d_in[13];
    const float* g1  = (const float*)d_in[14]; const float* be1 = (const float*)d_in[15];
    const float* W2  = (const float*)d_in[16]; const float* b2  = (const float*)d_in[17];
    const float* g2  = (const float*)d_in[18]; const float* be2 = (const float*)d_in[19];
    const float* W3  = (const float*)d_in[20]; const float* b3  = (const float*)d_in[21];
    const int*   ei  = (const int*)d_in[22];
    float* out = (float*)d_out;

    cudaFuncSetAttribute(conv_kernel, cudaFuncAttributeMaxDynamicSharedMemorySize, CONV_SMEM_BYTES);
    cudaFuncSetAttribute(mlp_kernel,  cudaFuncAttributeMaxDynamicSharedMemorySize, MLP_SMEM_BYTES);

    prep_kernel<<<179, 256>>>(ei, ew, W1, W2);
    conv_kernel<<<BATCH, 256, CONV_SMEM_BYTES>>>(state, pos, Wq, bq, Wk, bk, Wv, bv, We, Wsk, bsk);
    mlp_kernel<<<NROWS / 64, 256, MLP_SMEM_BYTES>>>(b1, g1, be1, b2, g2, be2, W3, b3);
    final_kernel<<<BATCH, 128>>>(out);
}

// round 5
// speedup vs baseline: 1.1968x; 1.0423x over previous
#include <cuda_runtime.h>
#include <cstdint>

typedef unsigned long long ull;

#define BATCH 256
#define NNODE 79
#define HID 256
#define NEDGE 3000
#define KP1 104                 // 97 inputs padded to 104 (13 panels of 8)
#define NROWS (BATCH*NNODE)     // 20224
#define NCH 24
#define CHSZ 125
#define NCELL (NNODE*NCH)       // 1896

// ---------------- device scratch ----------------
__device__ int   g_srcp[NEDGE];
__device__ int   g_dstp[NEDGE];
__device__ float g_ewp[NEDGE];
__device__ int   g_rowptr[NNODE + 1];
__device__ float g_W1U[KP1 * HID];       // k-major, un-duplicated
__device__ float g_W2U[HID * HID];
__device__ float g_hin[(size_t)NROWS * KP1];
__device__ float g_conc[NROWS];

__device__ __forceinline__ float wredsum(float v) {
    #pragma unroll
    for (int o = 16; o; o >>= 1) v += __shfl_xor_sync(0xffffffffu, v, o);
    return v;
}
__device__ __forceinline__ float wredmax(float v) {
    #pragma unroll
    for (int o = 16; o; o >>= 1) v = fmaxf(v, __shfl_xor_sync(0xffffffffu, v, o));
    return v;
}

// ---- packed fp32x2 helpers ----
__device__ __forceinline__ ull dup2(float v) {
    ull r; asm("mov.b64 %0,{%1,%1};" : "=l"(r) : "f"(v)); return r;
}
__device__ __forceinline__ ull pk2(float a, float b) {
    ull r; asm("mov.b64 %0,{%1,%2};" : "=l"(r) : "f"(a), "f"(b)); return r;
}
__device__ __forceinline__ ull f2fma(ull a, ull b, ull c) {
    ull d; asm("fma.rn.f32x2 %0,%1,%2,%3;" : "=l"(d) : "l"(a), "l"(b), "l"(c)); return d;
}
__device__ __forceinline__ void up2(ull v, float& lo, float& hi) {
    asm("mov.b64 {%0,%1},%2;" : "=f"(lo), "=f"(hi) : "l"(v));
}
__device__ __forceinline__ void cpasync16(uint32_t saddr, const float* g) {
    asm volatile("cp.async.ca.shared.global [%0], [%1], 16;" :: "r"(saddr), "l"(g));
}

// ---------------- prep: block0 = CSR sort; blocks 1.. = weight transpose ----------------
__global__ __launch_bounds__(256) void prep_kernel(const int* __restrict__ ei,
                                                   const float* __restrict__ ew,
                                                   const float* __restrict__ W1,
                                                   const float* __restrict__ W2) {
    int tid = threadIdx.x;
    if (blockIdx.x == 0) {
        __shared__ int dsts[NEDGE];
        __shared__ int cell[NCELL];
        __shared__ int wsum[8];
        int lane = tid & 31, w = tid >> 5;
        for (int e = tid; e < NEDGE; e += 256) dsts[e] = ei[NEDGE + e];
        for (int c = tid; c < NCELL; c += 256) cell[c] = 0;
        __syncthreads();
        for (int e = tid; e < NEDGE; e += 256)
            atomicAdd(&cell[dsts[e] * NCH + e / CHSZ], 1);   // int atomics: deterministic
        __syncthreads();
        int base = tid * 8, loc[8], s = 0;
        #pragma unroll
        for (int j = 0; j < 8; j++) {
            int v = (base + j < NCELL) ? cell[base + j] : 0;
            loc[j] = s; s += v;
        }
        int x = s;
        #pragma unroll
        for (int o = 1; o < 32; o <<= 1) {
            int t = __shfl_up_sync(0xffffffffu, x, o);
            if (lane >= o) x += t;
        }
        if (lane == 31) wsum[w] = x;
        int exw = x - s;
        __syncthreads();
        if (tid == 0) {
            int a = 0;
            for (int i = 0; i < 8; i++) { int t = wsum[i]; wsum[i] = a; a += t; }
        }
        __syncthreads();
        int off = wsum[w] + exw;
        #pragma unroll
        for (int j = 0; j < 8; j++) if (base + j < NCELL) cell[base + j] = off + loc[j];
        __syncthreads();
        if (tid < NNODE) g_rowptr[tid] = cell[tid * NCH];
        if (tid == 0) g_rowptr[NNODE] = NEDGE;
        for (int e = tid; e < NEDGE; e += 256) {
            int d = dsts[e];
            int ch = e / CHSZ, b0 = ch * CHSZ;
            int rank = 0;
            for (int e2 = b0; e2 < e; e2++) rank += (dsts[e2] == d);
            int pos = cell[d * NCH + ch] + rank;
            g_dstp[pos] = d; g_srcp[pos] = ei[e]; g_ewp[pos] = ew[e];
        }
    } else {
        int gtid = (blockIdx.x - 1) * 256 + tid, gs = (gridDim.x - 1) * 256;
        for (int t = gtid; t < KP1 * HID; t += gs) {
            int k = t >> 8, j = t & 255;
            g_W1U[t] = (k < 97) ? W1[j * 97 + k] : 0.f;
        }
        for (int t = gtid; t < HID * HID; t += gs) {
            int k = t >> 8, j = t & 255;
            g_W2U[t] = W2[j * HID + k];
        }
    }
}

// ---------------- conv: one CTA per batch; 2 CTAs/SM ----------------
#define CONV_SMEM_FLOATS (2640 + 2*2080 + 3*5056 + 3000 + 80 + 64 + 4 + 80)
#define CONV_SMEM_BYTES  (CONV_SMEM_FLOATS * 4)

__global__ __launch_bounds__(256) void conv_kernel(
    const float* __restrict__ state, const float* __restrict__ pos,
    const float* __restrict__ Wq, const float* __restrict__ bq,
    const float* __restrict__ Wk, const float* __restrict__ bk,
    const float* __restrict__ Wv, const float* __restrict__ bv,
    const float* __restrict__ We,
    const float* __restrict__ Wsk, const float* __restrict__ bsk) {
    extern __shared__ float sm[];
    float* xs  = sm;              // 80*33
    float* WA  = xs + 2640;       // 32*65 k-major
    float* WB  = WA + 2080;
    float* qs  = WB + 2080;       // 79*64
    float* ks  = qs + 5056;
    float* vs  = ks + 5056;
    float* alp = vs + 5056;       // 3000
    float* qWe = alp + 3000;      // 80
    float* wes = qWe + 80;        // 64
    float* tot = wes + 64;        // 4
    int*   rps = (int*)(tot + 4); // 80

    int b = blockIdx.x, tid = threadIdx.x, lane = tid & 31, w = tid >> 5;

    for (int idx = tid; idx < 80 * 32; idx += 256) {
        int i = idx >> 5, k = idx & 31;
        float v = 0.f;
        if (i < NNODE) v = (k < 26) ? state[((size_t)b * NNODE + i) * 26 + k]
                                    : pos[i * 6 + (k - 26)];
        xs[i * 33 + k] = v;
    }
    for (int idx = tid; idx < 64 * 32; idx += 256) {
        int d = idx >> 5, k = idx & 31;
        WA[k * 65 + d] = Wq[idx];
        WB[k * 65 + d] = Wk[idx];
    }
    if (tid <= NNODE) rps[tid] = g_rowptr[tid];
    if (tid < 64) wes[tid] = We[tid];
    __syncthreads();

    if (tid == 0) {
        float t = 0.f;
        for (int i = 0; i < NNODE; i++) t += xs[i * 33 + 1];
        tot[0] = t;
    }
    #pragma unroll 1
    for (int it = 0; it < 5; it++) {
        int item = tid + it * 256;
        int d = item & 63, i0 = (item >> 6) << 2;
        float aq[4] = {0,0,0,0}, ak[4] = {0,0,0,0};
        #pragma unroll 8
        for (int k = 0; k < 32; k++) {
            float wq = WA[k * 65 + d], wk = WB[k * 65 + d];
            #pragma unroll
            for (int n = 0; n < 4; n++) {
                float xv = xs[(i0 + n) * 33 + k];
                aq[n] += xv * wq; ak[n] += xv * wk;
            }
        }
        float bqv = __ldg(bq + d), bkv = __ldg(bk + d);
        #pragma unroll
        for (int n = 0; n < 4; n++) {
            if (i0 + n < NNODE) {
                qs[(i0 + n) * 64 + d] = aq[n] + bqv;
                ks[(i0 + n) * 64 + d] = ak[n] + bkv;
            }
        }
    }
    __syncthreads();

    if (tid < NNODE) {
        float a = 0.f;
        const float* qr = qs + tid * 64;
        #pragma unroll 8
        for (int d = 0; d < 64; d++) a += qr[d] * wes[d];
        qWe[tid] = a;
    }
    for (int idx = tid; idx < 64 * 32; idx += 256) {
        int d = idx >> 5, k = idx & 31;
        WA[k * 65 + d] = Wv[idx];
        WB[k * 65 + d] = Wsk[idx];
    }
    // hin tail cols 64..103: [64]=total, [65..96]=x, [97..103]=0
    for (int idx = tid; idx < NNODE * 40; idx += 256) {
        int i = idx / 40, c = idx - i * 40;
        size_t r = (size_t)b * NNODE + i;
        float v;
        if (c == 0) v = tot[0];
        else if (c <= 32) v = xs[i * 33 + (c - 1)];
        else v = 0.f;
        g_hin[r * KP1 + 64 + c] = v;
    }
    __syncthreads();

    #pragma unroll 1
    for (int it = 0; it < 5; it++) {
        int item = tid + it * 256;
        int d = item & 63, i0 = (item >> 6) << 2;
        float av[4] = {0,0,0,0}, as[4] = {0,0,0,0};
        #pragma unroll 8
        for (int k = 0; k < 32; k++) {
            float wv = WA[k * 65 + d], ws = WB[k * 65 + d];
            #pragma unroll
            for (int n = 0; n < 4; n++) {
                float xv = xs[(i0 + n) * 33 + k];
                av[n] += xv * wv; as[n] += xv * ws;
            }
        }
        float bvv = __ldg(bv + d), bsv = __ldg(bsk + d);
        #pragma unroll
        for (int n = 0; n < 4; n++) {
            if (i0 + n < NNODE) {
                vs[(i0 + n) * 64 + d] = av[n] + bvv;
                g_hin[((size_t)b * NNODE + i0 + n) * KP1 + d] = as[n] + bsv;
            }
        }
    }
    {
        int g = lane >> 3, li = lane & 7;
        for (int e = w * 4 + g; e < NEDGE; e += 32) {
            int dd = g_dstp[e], ss = g_srcp[e];
            float ewv = g_ewp[e];
            const float4* qr = (const float4*)(qs + dd * 64 + li * 8);
            const float4* kr = (const float4*)(ks + ss * 64 + li * 8);
            float4 q0 = qr[0], q1 = qr[1], k0 = kr[0], k1 = kr[1];
            float p = q0.x*k0.x + q0.y*k0.y + q0.z*k0.z + q0.w*k0.w
                    + q1.x*k1.x + q1.y*k1.y + q1.z*k1.z + q1.w*k1.w;
            p += __shfl_xor_sync(0xffffffffu, p, 1);
            p += __shfl_xor_sync(0xffffffffu, p, 2);
            p += __shfl_xor_sync(0xffffffffu, p, 4);
            if (li == 0) alp[e] = 0.125f * (p + ewv * qWe[dd]);
        }
    }
    __syncthreads();

    float we0 = wes[lane], we1 = wes[lane + 32];
    for (int i = w; i < NNODE; i += 8) {
        int s0 = rps[i], e1 = rps[i + 1];
        float a0 = 0.f, a1 = 0.f;
        if (e1 > s0) {
            float m = -1e30f;
            for (int e = s0 + lane; e < e1; e += 32) m = fmaxf(m, alp[e]);
            m = wredmax(m);
            float den = 0.f;
            for (int e = s0 + lane; e < e1; e += 32) {
                float ex = __expf(alp[e] - m);
                alp[e] = ex; den += ex;
            }
            den = wredsum(den);
            float inv = 1.f / (den + 1e-16f);
            float sew = 0.f;
            for (int e = s0; e < e1; e++) {
                float wg = alp[e] * inv;
                int ss = g_srcp[e];
                a0 += wg * vs[ss * 64 + lane];
                a1 += wg * vs[ss * 64 + lane + 32];
                sew += wg * g_ewp[e];
            }
            a0 += sew * we0; a1 += sew * we1;
        }
        size_t r = (size_t)b * NNODE + i;
        float s0v = g_hin[r * KP1 + lane];
        float s1v = g_hin[r * KP1 + lane + 32];
        g_hin[r * KP1 + lane]      = fmaxf(a0 + s0v, 0.f);
        g_hin[r * KP1 + lane + 32] = fmaxf(a1 + s1v, 0.f);
    }
}

// ---------------- MLP: f32x2, 128 rows/CTA, 512 threads, smem-staged weights ----------------
// smem floats: xs 13312 | hb 32768 | wp 4096 | mu 128 | rsd 128 | w3 256
#define MLP_SMEM_FLOATS (13312 + 32768 + 4096 + 128 + 128 + 256)
#define MLP_SMEM_BYTES  (MLP_SMEM_FLOATS * 4)

// K-panel pipelined GEMM: acc[c][rp] accumulates rows (2*(pbase+rp), +1) x channels 4c4+c
template<int K>
__device__ __forceinline__ void gemm_panels(const float* __restrict__ Wg,
                                            const float* __restrict__ xsrc,
                                            float* __restrict__ wp, uint32_t wp_s32,
                                            float4 bvv, ull (&acc)[4][8],
                                            int c4, int pbase, int tid) {
    const int NP = K / 8;
    cpasync16(wp_s32 + tid * 16, Wg + tid * 4);
    asm volatile("cp.async.commit_group;");
    #pragma unroll
    for (int rp = 0; rp < 8; rp++) {
        acc[0][rp] = dup2(bvv.x); acc[1][rp] = dup2(bvv.y);
        acc[2][rp] = dup2(bvv.z); acc[3][rp] = dup2(bvv.w);
    }
    const float* xb = xsrc + (size_t)pbase * K * 2;
    #pragma unroll 1
    for (int p = 0; p < NP; p++) {
        if (p + 1 < NP) {
            cpasync16(wp_s32 + ((p + 1) & 1) * 8192 + tid * 16, Wg + (p + 1) * 2048 + tid * 4);
            asm volatile("cp.async.commit_group;");
            asm volatile("cp.async.wait_group 1;");
        } else {
            asm volatile("cp.async.wait_group 0;");
        }
        __syncthreads();
        const float* wb = wp + (p & 1) * 2048;
        #pragma unroll
        for (int kk2 = 0; kk2 < 4; kk2++) {
            int kl = kk2 * 2;
            float4 wa = *(const float4*)(wb + kl * 256 + 4 * c4);
            float4 wc = *(const float4*)(wb + (kl + 1) * 256 + 4 * c4);
            ull a0 = dup2(wa.x), a1 = dup2(wa.y), a2 = dup2(wa.z), a3 = dup2(wa.w);
            ull c0 = dup2(wc.x), c1 = dup2(wc.y), c2 = dup2(wc.z), c3 = dup2(wc.w);
            int kg = p * 8 + kl;
            #pragma unroll
            for (int rp = 0; rp < 8; rp++) {
                ulonglong2 xv = *(const ulonglong2*)(xb + ((size_t)rp * K + kg) * 2);
                acc[0][rp] = f2fma(xv.x, a0, acc[0][rp]);
                acc[1][rp] = f2fma(xv.x, a1, acc[1][rp]);
                acc[2][rp] = f2fma(xv.x, a2, acc[2][rp]);
                acc[3][rp] = f2fma(xv.x, a3, acc[3][rp]);
                acc[0][rp] = f2fma(xv.y, c0, acc[0][rp]);
                acc[1][rp] = f2fma(xv.y, c1, acc[1][rp]);
                acc[2][rp] = f2fma(xv.y, c2, acc[2][rp]);
                acc[3][rp] = f2fma(xv.y, c3, acc[3][rp]);
            }
        }
        __syncthreads();
    }
}

__global__ __launch_bounds__(512, 1) void mlp_kernel(
    const float* __restrict__ b1, const float* __restrict__ g1, const float* __restrict__ be1,
    const float* __restrict__ b2, const float* __restrict__ g2, const float* __restrict__ be2,
    const float* __restrict__ W3, const float* __restrict__ b3) {
    extern __shared__ float sm[];
    float* xs  = sm;                  // 64 pr x 104 k x 2
    float* hb  = xs + 13312;          // 64 pr x 256 ch x 2
    float* wp  = hb + 32768;          // 2 x 8 x 256 weight panels
    float* mu  = wp + 4096;           // 128
    float* rsd = mu + 128;            // 128
    float* w3s = rsd + 128;           // 256
    ull* hbp = (ull*)hb;
    uint32_t wp_s32 = (uint32_t)__cvta_generic_to_shared(wp);
    int tid = threadIdx.x, lane = tid & 31, w = tid >> 5;
    int c4 = tid & 63, pbase = (tid >> 6) * 8;
    size_t row0 = (size_t)blockIdx.x * 128;

    // load x pair-interleaved (104 = 26 float4 per row)
    {
        const float4* src4 = (const float4*)(g_hin + row0 * KP1);
        for (int i = tid; i < 128 * 26; i += 512) {
            int r = i / 26, q = i - r * 26;
            float4 f = src4[i];
            float* d = xs + ((r >> 1) * KP1 + 4 * q) * 2 + (r & 1);
            d[0] = f.x; d[2] = f.y; d[4] = f.z; d[6] = f.w;
        }
    }
    if (tid < 256) w3s[tid] = W3[tid];
    __syncthreads();

    ull acc[4][8];
    // ---- layer 1 ----
    gemm_panels<KP1>(g_W1U, xs, wp, wp_s32, ((const float4*)b1)[c4], acc, c4, pbase, tid);
    #pragma unroll
    for (int rp = 0; rp < 8; rp++)
        #pragma unroll
        for (int c = 0; c < 4; c++)
            hbp[(size_t)(pbase + rp) * HID + 4 * c4 + c] = acc[c][rp];
    __syncthreads();
    for (int r = w; r < 128; r += 16) {
        int pr = r >> 1, par = r & 1;
        float s = 0.f, s2 = 0.f;
        #pragma unroll
        for (int t = 0; t < 8; t++) {
            float v = hb[((size_t)pr * HID + lane + t * 32) * 2 + par];
            s += v; s2 += v * v;
        }
        s = wredsum(s); s2 = wredsum(s2);
        if (lane == 0) {
            float m = s * (1.f / HID);
            mu[r] = m;
            rsd[r] = rsqrtf(s2 * (1.f / HID) - m * m + 1e-5f);
        }
    }
    __syncthreads();
    {
        float4 gv = ((const float4*)g1)[c4], bev = ((const float4*)be1)[c4];
        float ga[4] = {gv.x, gv.y, gv.z, gv.w}, ba[4] = {bev.x, bev.y, bev.z, bev.w};
        #pragma unroll
        for (int rp = 0; rp < 8; rp++) {
            int pr = pbase + rp;
            float m0 = mu[2*pr], m1 = mu[2*pr+1], r0 = rsd[2*pr], r1 = rsd[2*pr+1];
            #pragma unroll
            for (int c = 0; c < 4; c++) {
                float lo, hi; up2(acc[c][rp], lo, hi);
                float h0 = (lo - m0) * r0 * ga[c] + ba[c];
                float h1 = (hi - m1) * r1 * ga[c] + ba[c];
                h0 = h0 > 0.f ? h0 : 0.01f * h0;
                h1 = h1 > 0.f ? h1 : 0.01f * h1;
                hbp[(size_t)pr * HID + 4 * c4 + c] = pk2(h0, h1);
            }
        }
    }
    __syncthreads();

    // ---- layer 2 ----
    gemm_panels<HID>(g_W2U, hb, wp, wp_s32, ((const float4*)b2)[c4], acc, c4, pbase, tid);
    #pragma unroll
    for (int rp = 0; rp < 8; rp++)
        #pragma unroll
        for (int c = 0; c < 4; c++)
            hbp[(size_t)(pbase + rp) * HID + 4 * c4 + c] = acc[c][rp];
    __syncthreads();
    for (int r = w; r < 128; r += 16) {
        int pr = r >> 1, par = r & 1;
        float s = 0.f, s2 = 0.f;
        #pragma unroll
        for (int t = 0; t < 8; t++) {
            float v = hb[((size_t)pr * HID + lane + t * 32) * 2 + par];
            s += v; s2 += v * v;
        }
        s = wredsum(s); s2 = wredsum(s2);
        if (lane == 0) {
            float m = s * (1.f / HID);
            mu[r] = m;
            rsd[r] = rsqrtf(s2 * (1.f / HID) - m * m + 1e-5f);
        }
    }
    __syncthreads();
    {
        float4 gv = ((const float4*)g2)[c4], bev = ((const float4*)be2)[c4];
        float ga[4] = {gv.x, gv.y, gv.z, gv.w}, ba[4] = {bev.x, bev.y, bev.z, bev.w};
        #pragma unroll
        for (int rp = 0; rp < 8; rp++) {
            int pr = pbase + rp;
            float m0 = mu[2*pr], m1 = mu[2*pr+1], r0 = rsd[2*pr], r1 = rsd[2*pr+1];
            #pragma unroll
            for (int c = 0; c < 4; c++) {
                float lo, hi; up2(acc[c][rp], lo, hi);
                float w3c = w3s[4 * c4 + c];
                float h0 = (lo - m0) * r0 * ga[c] + ba[c];
                float h1 = (hi - m1) * r1 * ga[c] + ba[c];
                h0 = h0 > 0.f ? h0 : 0.01f * h0;
                h1 = h1 > 0.f ? h1 : 0.01f * h1;
                hbp[(size_t)pr * HID + 4 * c4 + c] = pk2(h0 * w3c, h1 * w3c);
            }
        }
    }
    __syncthreads();
    float b3v = b3[0];
    for (int r = w; r < 128; r += 16) {
        int pr = r >> 1, par = r & 1;
        float s = 0.f;
        #pragma unroll
        for (int t = 0; t < 8; t++)
            s += hb[((size_t)pr * HID + lane + t * 32) * 2 + par];
        s = wredsum(s);
        if (lane == 0) {
            float yv = s + b3v;
            g_conc[row0 + r] = (yv > 20.f) ? yv : log1pf(expf(yv));
        }
    }
}

// ---------------- final normalize per batch ----------------
__global__ __launch_bounds__(128) void final_kernel(float* __restrict__ out) {
    __shared__ float sb[4];
    int b = blockIdx.x, tid = threadIdx.x, lane = tid & 31, w = tid >> 5;
    float v = (tid < NNODE) ? g_conc[b * NNODE + tid] : 0.f;
    float s = v;
    #pragma unroll
    for (int o = 16; o; o >>= 1) s += __shfl_xor_sync(0xffffffffu, s, o);
    if (lane == 0) sb[w] = s;
    __syncthreads();
    float tt = sb[0] + sb[1] + sb[2] + sb[3];
    if (tid < NNODE) out[b * NNODE + tid] = v / (tt + 1e-20f);
}

// ---------------- launch ----------------
extern "C" void kernel_launch(void* const* d_in, const int* in_sizes, int n_in,
                              void* d_out, int out_size) {
    const float* state = (const float*)d_in[0];
    const float* pos   = (const float*)d_in[1];
    const float* ew    = (const float*)d_in[2];
    const float* Wq  = (const float*)d_in[3];  const float* bq  = (const float*)d_in[4];
    const float* Wk  = (const float*)d_in[5];  const float* bk  = (const float*)d_in[6];
    const float* Wv  = (const float*)d_in[7];  const float* bv  = (const float*)d_in[8];
    const float* We  = (const float*)d_in[9];
    const float* Wsk = (const float*)d_in[10]; const float* bsk = (const float*)d_in[11];
    const float* W1  = (const float*)d_in[12]; const float* b1  = (const float*)d_in[13];
    const float* g1  = (const float*)d_in[14]; const float* be1 = (const float*)d_in[15];
    const float* W2  = (const float*)d_in[16]; const float* b2  = (const float*)d_in[17];
    const float* g2  = (const float*)d_in[18]; const float* be2 = (const float*)d_in[19];
    const float* W3  = (const float*)d_in[20]; const float* b3  = (const float*)d_in[21];
    const int*   ei  = (const int*)d_in[22];
    float* out = (float*)d_out;

    cudaFuncSetAttribute(conv_kernel, cudaFuncAttributeMaxDynamicSharedMemorySize, CONV_SMEM_BYTES);
    cudaFuncSetAttribute(mlp_kernel,  cudaFuncAttributeMaxDynamicSharedMemorySize, MLP_SMEM_BYTES);

    prep_kernel<<<179, 256>>>(ei, ew, W1, W2);
    conv_kernel<<<BATCH, 256, CONV_SMEM_BYTES>>>(state, pos, Wq, bq, Wk, bk, Wv, bv, We, Wsk, bsk);
    mlp_kernel<<<NROWS / 128, 512, MLP_SMEM_BYTES>>>(b1, g1, be1, b2, g2, be2, W3, b3);
    final_kernel<<<BATCH, 128>>>(out);
}

// round 6
// speedup vs baseline: 1.2516x; 1.0458x over previous
#include <cuda_runtime.h>
#include <cstdint>

typedef unsigned long long ull;

#define BATCH 256
#define NNODE 79
#define HID 256
#define NEDGE 3000
#define KP1 104                 // 97 inputs padded to 104 (13 panels of 8)
#define NROWS (BATCH*NNODE)     // 20224
#define NCH 24
#define CHSZ 125
#define NCELL (NNODE*NCH)       // 1896

// ---------------- device scratch ----------------
__device__ int   g_srcp[NEDGE];
__device__ int   g_dstp[NEDGE];
__device__ float g_ewp[NEDGE];
__device__ int   g_rowptr[NNODE + 1];
__device__ float g_W1U[KP1 * HID];       // k-major, un-duplicated
__device__ float g_W2U[HID * HID];
__device__ float g_hin[(size_t)NROWS * KP1];
__device__ float g_conc[NROWS];

__device__ __forceinline__ float wredsum(float v) {
    #pragma unroll
    for (int o = 16; o; o >>= 1) v += __shfl_xor_sync(0xffffffffu, v, o);
    return v;
}
__device__ __forceinline__ float wredmax(float v) {
    #pragma unroll
    for (int o = 16; o; o >>= 1) v = fmaxf(v, __shfl_xor_sync(0xffffffffu, v, o));
    return v;
}

// ---- packed fp32x2 helpers ----
__device__ __forceinline__ ull dup2(float v) {
    ull r; asm("mov.b64 %0,{%1,%1};" : "=l"(r) : "f"(v)); return r;
}
__device__ __forceinline__ ull pk2(float a, float b) {
    ull r; asm("mov.b64 %0,{%1,%2};" : "=l"(r) : "f"(a), "f"(b)); return r;
}
__device__ __forceinline__ ull f2fma(ull a, ull b, ull c) {
    ull d; asm("fma.rn.f32x2 %0,%1,%2,%3;" : "=l"(d) : "l"(a), "l"(b), "l"(c)); return d;
}
__device__ __forceinline__ void up2(ull v, float& lo, float& hi) {
    asm("mov.b64 {%0,%1},%2;" : "=f"(lo), "=f"(hi) : "l"(v));
}
__device__ __forceinline__ void cpasync16(uint32_t saddr, const float* g) {
    asm volatile("cp.async.ca.shared.global [%0], [%1], 16;" :: "r"(saddr), "l"(g));
}

// ---------------- prep: block0 = CSR sort; blocks 1.. = weight transpose ----------------
__global__ __launch_bounds__(256) void prep_kernel(const int* __restrict__ ei,
                                                   const float* __restrict__ ew,
                                                   const float* __restrict__ W1,
                                                   const float* __restrict__ W2) {
    int tid = threadIdx.x;
    if (blockIdx.x == 0) {
        __shared__ int dsts[NEDGE];
        __shared__ int cell[NCELL];
        __shared__ int wsum[8];
        int lane = tid & 31, w = tid >> 5;
        for (int e = tid; e < NEDGE; e += 256) dsts[e] = ei[NEDGE + e];
        for (int c = tid; c < NCELL; c += 256) cell[c] = 0;
        __syncthreads();
        for (int e = tid; e < NEDGE; e += 256)
            atomicAdd(&cell[dsts[e] * NCH + e / CHSZ], 1);   // int atomics: deterministic
        __syncthreads();
        int base = tid * 8, loc[8], s = 0;
        #pragma unroll
        for (int j = 0; j < 8; j++) {
            int v = (base + j < NCELL) ? cell[base + j] : 0;
            loc[j] = s; s += v;
        }
        int x = s;
        #pragma unroll
        for (int o = 1; o < 32; o <<= 1) {
            int t = __shfl_up_sync(0xffffffffu, x, o);
            if (lane >= o) x += t;
        }
        if (lane == 31) wsum[w] = x;
        int exw = x - s;
        __syncthreads();
        if (tid == 0) {
            int a = 0;
            for (int i = 0; i < 8; i++) { int t = wsum[i]; wsum[i] = a; a += t; }
        }
        __syncthreads();
        int off = wsum[w] + exw;
        #pragma unroll
        for (int j = 0; j < 8; j++) if (base + j < NCELL) cell[base + j] = off + loc[j];
        __syncthreads();
        if (tid < NNODE) g_rowptr[tid] = cell[tid * NCH];
        if (tid == 0) g_rowptr[NNODE] = NEDGE;
        for (int e = tid; e < NEDGE; e += 256) {
            int d = dsts[e];
            int ch = e / CHSZ, b0 = ch * CHSZ;
            int rank = 0;
            for (int e2 = b0; e2 < e; e2++) rank += (dsts[e2] == d);
            int pos = cell[d * NCH + ch] + rank;
            g_dstp[pos] = d; g_srcp[pos] = ei[e]; g_ewp[pos] = ew[e];
        }
    } else {
        int gtid = (blockIdx.x - 1) * 256 + tid, gs = (gridDim.x - 1) * 256;
        for (int t = gtid; t < KP1 * HID; t += gs) {
            int k = t >> 8, j = t & 255;
            g_W1U[t] = (k < 97) ? W1[j * 97 + k] : 0.f;
        }
        for (int t = gtid; t < HID * HID; t += gs) {
            int k = t >> 8, j = t & 255;
            g_W2U[t] = W2[j * HID + k];
        }
    }
}

// ---------------- conv: one CTA per batch; 2 CTAs/SM ----------------
// floats: xs 2640 | WA 2080 | WB 2080 | qs/ks/vs 3*5056 | alp 3000 | qWe 80 | wes 64
//         | tot 4 | rps 80 | srcp_s 1500 (3000 i16) | dstp_s 1500 (3000 i16)
#define CONV_SMEM_FLOATS (2640 + 2*2080 + 3*5056 + 3000 + 80 + 64 + 4 + 80 + 1500 + 1500)
#define CONV_SMEM_BYTES  (CONV_SMEM_FLOATS * 4)

__global__ __launch_bounds__(256, 2) void conv_kernel(
    const float* __restrict__ state, const float* __restrict__ pos,
    const float* __restrict__ Wq, const float* __restrict__ bq,
    const float* __restrict__ Wk, const float* __restrict__ bk,
    const float* __restrict__ Wv, const float* __restrict__ bv,
    const float* __restrict__ We,
    const float* __restrict__ Wsk, const float* __restrict__ bsk) {
    extern __shared__ float sm[];
    float* xs  = sm;              // 80*33
    float* WA  = xs + 2640;       // 32*65 k-major
    float* WB  = WA + 2080;
    float* qs  = WB + 2080;       // 79*64
    float* ks  = qs + 5056;
    float* vs  = ks + 5056;
    float* alp = vs + 5056;       // 3000
    float* qWe = alp + 3000;      // 80
    float* wes = qWe + 80;        // 64
    float* tot = wes + 64;        // 4
    int*   rps = (int*)(tot + 4); // 80
    short* srcp_s = (short*)(rps + 80);       // 3000
    short* dstp_s = srcp_s + 3000;            // 3000

    int b = blockIdx.x, tid = threadIdx.x, lane = tid & 31, w = tid >> 5;

    // phase 1: stage x, Wq/Wk, indices (int16), rowptr, We
    for (int idx = tid; idx < 80 * 32; idx += 256) {
        int i = idx >> 5, k = idx & 31;
        float v = 0.f;
        if (i < NNODE) v = (k < 26) ? state[((size_t)b * NNODE + i) * 26 + k]
                                    : pos[i * 6 + (k - 26)];
        xs[i * 33 + k] = v;
    }
    for (int idx = tid; idx < 64 * 32; idx += 256) {
        int d = idx >> 5, k = idx & 31;
        WA[k * 65 + d] = Wq[idx];
        WB[k * 65 + d] = Wk[idx];
    }
    for (int e = tid; e < NEDGE; e += 256) {
        srcp_s[e] = (short)g_srcp[e];
        dstp_s[e] = (short)g_dstp[e];
    }
    if (tid <= NNODE) rps[tid] = g_rowptr[tid];
    if (tid < 64) wes[tid] = We[tid];
    __syncthreads();

    // phase 2: total agents + GEMM A (q,k)
    if (tid == 0) {
        float t = 0.f;
        for (int i = 0; i < NNODE; i++) t += xs[i * 33 + 1];
        tot[0] = t;
    }
    #pragma unroll 1
    for (int it = 0; it < 5; it++) {
        int item = tid + it * 256;
        int d = item & 63, i0 = (item >> 6) << 2;
        float aq[4] = {0,0,0,0}, ak[4] = {0,0,0,0};
        #pragma unroll 8
        for (int k = 0; k < 32; k++) {
            float wq = WA[k * 65 + d], wk = WB[k * 65 + d];
            #pragma unroll
            for (int n = 0; n < 4; n++) {
                float xv = xs[(i0 + n) * 33 + k];
                aq[n] += xv * wq; ak[n] += xv * wk;
            }
        }
        float bqv = __ldg(bq + d), bkv = __ldg(bk + d);
        #pragma unroll
        for (int n = 0; n < 4; n++) {
            if (i0 + n < NNODE) {
                qs[(i0 + n) * 64 + d] = aq[n] + bqv;
                ks[(i0 + n) * 64 + d] = ak[n] + bkv;
            }
        }
    }
    __syncthreads();

    // phase 3: qWe, restage Wv/Wsk, hin tail
    if (tid < NNODE) {
        float a = 0.f;
        const float* qr = qs + tid * 64;
        #pragma unroll 8
        for (int d = 0; d < 64; d++) a += qr[d] * wes[d];
        qWe[tid] = a;
    }
    for (int idx = tid; idx < 64 * 32; idx += 256) {
        int d = idx >> 5, k = idx & 31;
        WA[k * 65 + d] = Wv[idx];
        WB[k * 65 + d] = Wsk[idx];
    }
    for (int idx = tid; idx < NNODE * 40; idx += 256) {
        int i = idx / 40, c = idx - i * 40;
        size_t r = (size_t)b * NNODE + i;
        float v;
        if (c == 0) v = tot[0];
        else if (c <= 32) v = xs[i * 33 + (c - 1)];
        else v = 0.f;
        g_hin[r * KP1 + 64 + c] = v;
    }
    __syncthreads();

    // phase 4: GEMM B (v -> smem, skip -> g_hin raw)
    #pragma unroll 1
    for (int it = 0; it < 5; it++) {
        int item = tid + it * 256;
        int d = item & 63, i0 = (item >> 6) << 2;
        float av[4] = {0,0,0,0}, as[4] = {0,0,0,0};
        #pragma unroll 8
        for (int k = 0; k < 32; k++) {
            float wv = WA[k * 65 + d], ws = WB[k * 65 + d];
            #pragma unroll
            for (int n = 0; n < 4; n++) {
                float xv = xs[(i0 + n) * 33 + k];
                av[n] += xv * wv; as[n] += xv * ws;
            }
        }
        float bvv = __ldg(bv + d), bsv = __ldg(bsk + d);
        #pragma unroll
        for (int n = 0; n < 4; n++) {
            if (i0 + n < NNODE) {
                vs[(i0 + n) * 64 + d] = av[n] + bvv;
                g_hin[((size_t)b * NNODE + i0 + n) * KP1 + d] = as[n] + bsv;
            }
        }
    }

    // phase 5: alpha — warp takes 4 contiguous edges, 8 lanes per edge
    {
        int g = lane >> 3, li = lane & 7;
        #pragma unroll 1
        for (int c0 = w; c0 < NEDGE / 4; c0 += 8) {
            int e = c0 * 4 + g;
            int dd = dstp_s[e], ss = srcp_s[e];
            float ewv = g_ewp[e];
            const float4* qr = (const float4*)(qs + dd * 64 + li * 8);
            const float4* kr = (const float4*)(ks + ss * 64 + li * 8);
            float4 q0 = qr[0], q1 = qr[1], k0 = kr[0], k1 = kr[1];
            float p = q0.x*k0.x + q0.y*k0.y + q0.z*k0.z + q0.w*k0.w
                    + q1.x*k1.x + q1.y*k1.y + q1.z*k1.z + q1.w*k1.w;
            p += __shfl_xor_sync(0xffffffffu, p, 1);
            p += __shfl_xor_sync(0xffffffffu, p, 2);
            p += __shfl_xor_sync(0xffffffffu, p, 4);
            if (li == 0) alp[e] = 0.125f * (p + ewv * qWe[dd]);
        }
    }
    __syncthreads();

    // phase 6: softmax + aggregation (warp per node), all edge data in smem
    float we0 = wes[lane], we1 = wes[lane + 32];
    for (int i = w; i < NNODE; i += 8) {
        int s0 = rps[i], e1 = rps[i + 1];
        float a0 = 0.f, a1 = 0.f;
        if (e1 > s0) {
            float m = -1e30f;
            for (int e = s0 + lane; e < e1; e += 32) m = fmaxf(m, alp[e]);
            m = wredmax(m);
            float den = 0.f, sew = 0.f;
            for (int e = s0 + lane; e < e1; e += 32) {
                float ex = __expf(alp[e] - m);
                alp[e] = ex; den += ex; sew += ex * g_ewp[e];
            }
            den = wredsum(den); sew = wredsum(sew);
            float inv = 1.f / (den + 1e-16f);
            float b0 = 0.f, b1 = 0.f;
            int e = s0;
            #pragma unroll 1
            for (; e + 1 < e1; e += 2) {
                float w0 = alp[e], w1v = alp[e + 1];
                int sA = srcp_s[e], sB = srcp_s[e + 1];
                a0 += w0 * vs[sA * 64 + lane];
                a1 += w0 * vs[sA * 64 + lane + 32];
                b0 += w1v * vs[sB * 64 + lane];
                b1 += w1v * vs[sB * 64 + lane + 32];
            }
            if (e < e1) {
                float w0 = alp[e]; int sA = srcp_s[e];
                a0 += w0 * vs[sA * 64 + lane];
                a1 += w0 * vs[sA * 64 + lane + 32];
            }
            a0 = (a0 + b0 + sew * we0) * inv;
            a1 = (a1 + b1 + sew * we1) * inv;
        }
        size_t r = (size_t)b * NNODE + i;
        float s0v = g_hin[r * KP1 + lane];
        float s1v = g_hin[r * KP1 + lane + 32];
        g_hin[r * KP1 + lane]      = fmaxf(a0 + s0v, 0.f);
        g_hin[r * KP1 + lane + 32] = fmaxf(a1 + s1v, 0.f);
    }
}

// ---------------- MLP: f32x2, 128 rows/CTA, 512 threads, smem-staged weights ----------------
#define MLP_SMEM_FLOATS (13312 + 32768 + 4096 + 128 + 128 + 256)
#define MLP_SMEM_BYTES  (MLP_SMEM_FLOATS * 4)

template<int K>
__device__ __forceinline__ void gemm_panels(const float* __restrict__ Wg,
                                            const float* __restrict__ xsrc,
                                            float* __restrict__ wp, uint32_t wp_s32,
                                            float4 bvv, ull (&acc)[4][8],
                                            int c4, int pbase, int tid) {
    const int NP = K / 8;
    cpasync16(wp_s32 + tid * 16, Wg + tid * 4);
    asm volatile("cp.async.commit_group;");
    #pragma unroll
    for (int rp = 0; rp < 8; rp++) {
        acc[0][rp] = dup2(bvv.x); acc[1][rp] = dup2(bvv.y);
        acc[2][rp] = dup2(bvv.z); acc[3][rp] = dup2(bvv.w);
    }
    const float* xb = xsrc + (size_t)pbase * K * 2;
    #pragma unroll 1
    for (int p = 0; p < NP; p++) {
        if (p + 1 < NP) {
            cpasync16(wp_s32 + ((p + 1) & 1) * 8192 + tid * 16, Wg + (p + 1) * 2048 + tid * 4);
            asm volatile("cp.async.commit_group;");
            asm volatile("cp.async.wait_group 1;");
        } else {
            asm volatile("cp.async.wait_group 0;");
        }
        __syncthreads();
        const float* wb = wp + (p & 1) * 2048;
        #pragma unroll
        for (int kk2 = 0; kk2 < 4; kk2++) {
            int kl = kk2 * 2;
            float4 wa = *(const float4*)(wb + kl * 256 + 4 * c4);
            float4 wc = *(const float4*)(wb + (kl + 1) * 256 + 4 * c4);
            ull a0 = dup2(wa.x), a1 = dup2(wa.y), a2 = dup2(wa.z), a3 = dup2(wa.w);
            ull c0 = dup2(wc.x), c1 = dup2(wc.y), c2 = dup2(wc.z), c3 = dup2(wc.w);
            int kg = p * 8 + kl;
            #pragma unroll
            for (int rp = 0; rp < 8; rp++) {
                ulonglong2 xv = *(const ulonglong2*)(xb + ((size_t)rp * K + kg) * 2);
                acc[0][rp] = f2fma(xv.x, a0, acc[0][rp]);
                acc[1][rp] = f2fma(xv.x, a1, acc[1][rp]);
                acc[2][rp] = f2fma(xv.x, a2, acc[2][rp]);
                acc[3][rp] = f2fma(xv.x, a3, acc[3][rp]);
                acc[0][rp] = f2fma(xv.y, c0, acc[0][rp]);
                acc[1][rp] = f2fma(xv.y, c1, acc[1][rp]);
                acc[2][rp] = f2fma(xv.y, c2, acc[2][rp]);
                acc[3][rp] = f2fma(xv.y, c3, acc[3][rp]);
            }
        }
        __syncthreads();
    }
}

__global__ __launch_bounds__(512, 1) void mlp_kernel(
    const float* __restrict__ b1, const float* __restrict__ g1, const float* __restrict__ be1,
    const float* __restrict__ b2, const float* __restrict__ g2, const float* __restrict__ be2,
    const float* __restrict__ W3, const float* __restrict__ b3) {
    extern __shared__ float sm[];
    float* xs  = sm;                  // 64 pr x 104 k x 2
    float* hb  = xs + 13312;          // 64 pr x 256 ch x 2
    float* wp  = hb + 32768;          // 2 x 8 x 256 weight panels
    float* mu  = wp + 4096;           // 128
    float* rsd = mu + 128;            // 128
    float* w3s = rsd + 128;           // 256
    ull* hbp = (ull*)hb;
    uint32_t wp_s32 = (uint32_t)__cvta_generic_to_shared(wp);
    int tid = threadIdx.x, lane = tid & 31, w = tid >> 5;
    int c4 = tid & 63, pbase = (tid >> 6) * 8;
    size_t row0 = (size_t)blockIdx.x * 128;

    {
        const float4* src4 = (const float4*)(g_hin + row0 * KP1);
        for (int i = tid; i < 128 * 26; i += 512) {
            int r = i / 26, q = i - r * 26;
            float4 f = src4[i];
            float* d = xs + ((r >> 1) * KP1 + 4 * q) * 2 + (r & 1);
            d[0] = f.x; d[2] = f.y; d[4] = f.z; d[6] = f.w;
        }
    }
    if (tid < 256) w3s[tid] = W3[tid];
    __syncthreads();

    ull acc[4][8];
    // ---- layer 1 ----
    gemm_panels<KP1>(g_W1U, xs, wp, wp_s32, ((const float4*)b1)[c4], acc, c4, pbase, tid);
    #pragma unroll
    for (int rp = 0; rp < 8; rp++)
        #pragma unroll
        for (int c = 0; c < 4; c++)
            hbp[(size_t)(pbase + rp) * HID + 4 * c4 + c] = acc[c][rp];
    __syncthreads();
    for (int r = w; r < 128; r += 16) {
        int pr = r >> 1, par = r & 1;
        float s = 0.f, s2 = 0.f;
        #pragma unroll
        for (int t = 0; t < 8; t++) {
            float v = hb[((size_t)pr * HID + lane + t * 32) * 2 + par];
            s += v; s2 += v * v;
        }
        s = wredsum(s); s2 = wredsum(s2);
        if (lane == 0) {
            float m = s * (1.f / HID);
            mu[r] = m;
            rsd[r] = rsqrtf(s2 * (1.f / HID) - m * m + 1e-5f);
        }
    }
    __syncthreads();
    {
        float4 gv = ((const float4*)g1)[c4], bev = ((const float4*)be1)[c4];
        float ga[4] = {gv.x, gv.y, gv.z, gv.w}, ba[4] = {bev.x, bev.y, bev.z, bev.w};
        #pragma unroll
        for (int rp = 0; rp < 8; rp++) {
            int pr = pbase + rp;
            float m0 = mu[2*pr], m1 = mu[2*pr+1], r0 = rsd[2*pr], r1 = rsd[2*pr+1];
            #pragma unroll
            for (int c = 0; c < 4; c++) {
                float lo, hi; up2(acc[c][rp], lo, hi);
                float h0 = (lo - m0) * r0 * ga[c] + ba[c];
                float h1 = (hi - m1) * r1 * ga[c] + ba[c];
                h0 = h0 > 0.f ? h0 : 0.01f * h0;
                h1 = h1 > 0.f ? h1 : 0.01f * h1;
                hbp[(size_t)pr * HID + 4 * c4 + c] = pk2(h0, h1);
            }
        }
    }
    __syncthreads();

    // ---- layer 2 ----
    gemm_panels<HID>(g_W2U, hb, wp, wp_s32, ((const float4*)b2)[c4], acc, c4, pbase, tid);
    #pragma unroll
    for (int rp = 0; rp < 8; rp++)
        #pragma unroll
        for (int c = 0; c < 4; c++)
            hbp[(size_t)(pbase + rp) * HID + 4 * c4 + c] = acc[c][rp];
    __syncthreads();
    for (int r = w; r < 128; r += 16) {
        int pr = r >> 1, par = r & 1;
        float s = 0.f, s2 = 0.f;
        #pragma unroll
        for (int t = 0; t < 8; t++) {
            float v = hb[((size_t)pr * HID + lane + t * 32) * 2 + par];
            s += v; s2 += v * v;
        }
        s = wredsum(s); s2 = wredsum(s2);
        if (lane == 0) {
            float m = s * (1.f / HID);
            mu[r] = m;
            rsd[r] = rsqrtf(s2 * (1.f / HID) - m * m + 1e-5f);
        }
    }
    __syncthreads();
    {
        float4 gv = ((const float4*)g2)[c4], bev = ((const float4*)be2)[c4];
        float ga[4] = {gv.x, gv.y, gv.z, gv.w}, ba[4] = {bev.x, bev.y, bev.z, bev.w};
        #pragma unroll
        for (int rp = 0; rp < 8; rp++) {
            int pr = pbase + rp;
            float m0 = mu[2*pr], m1 = mu[2*pr+1], r0 = rsd[2*pr], r1 = rsd[2*pr+1];
            #pragma unroll
            for (int c = 0; c < 4; c++) {
                float lo, hi; up2(acc[c][rp], lo, hi);
                float w3c = w3s[4 * c4 + c];
                float h0 = (lo - m0) * r0 * ga[c] + ba[c];
                float h1 = (hi - m1) * r1 * ga[c] + ba[c];
                h0 = h0 > 0.f ? h0 : 0.01f * h0;
                h1 = h1 > 0.f ? h1 : 0.01f * h1;
                hbp[(size_t)pr * HID + 4 * c4 + c] = pk2(h0 * w3c, h1 * w3c);
            }
        }
    }
    __syncthreads();
    float b3v = b3[0];
    for (int r = w; r < 128; r += 16) {
        int pr = r >> 1, par = r & 1;
        float s = 0.f;
        #pragma unroll
        for (int t = 0; t < 8; t++)
            s += hb[((size_t)pr * HID + lane + t * 32) * 2 + par];
        s = wredsum(s);
        if (lane == 0) {
            float yv = s + b3v;
            g_conc[row0 + r] = (yv > 20.f) ? yv : log1pf(expf(yv));
        }
    }
}

// ---------------- final normalize per batch ----------------
__global__ __launch_bounds__(128) void final_kernel(float* __restrict__ out) {
    __shared__ float sb[4];
    int b = blockIdx.x, tid = threadIdx.x, lane = tid & 31, w = tid >> 5;
    float v = (tid < NNODE) ? g_conc[b * NNODE + tid] : 0.f;
    float s = v;
    #pragma unroll
    for (int o = 16; o; o >>= 1) s += __shfl_xor_sync(0xffffffffu, s, o);
    if (lane == 0) sb[w] = s;
    __syncthreads();
    float tt = sb[0] + sb[1] + sb[2] + sb[3];
    if (tid < NNODE) out[b * NNODE + tid] = v / (tt + 1e-20f);
}

// ---------------- launch ----------------
extern "C" void kernel_launch(void* const* d_in, const int* in_sizes, int n_in,
                              void* d_out, int out_size) {
    const float* state = (const float*)d_in[0];
    const float* pos   = (const float*)d_in[1];
    const float* ew    = (const float*)d_in[2];
    const float* Wq  = (const float*)d_in[3];  const float* bq  = (const float*)d_in[4];
    const float* Wk  = (const float*)d_in[5];  const float* bk  = (const float*)d_in[6];
    const float* Wv  = (const float*)d_in[7];  const float* bv  = (const float*)d_in[8];
    const float* We  = (const float*)d_in[9];
    const float* Wsk = (const float*)d_in[10]; const float* bsk = (const float*)d_in[11];
    const float* W1  = (const float*)d_in[12]; const float* b1  = (const float*)d_in[13];
    const float* g1  = (const float*)d_in[14]; const float* be1 = (const float*)d_in[15];
    const float* W2  = (const float*)d_in[16]; const float* b2  = (const float*)d_in[17];
    const float* g2  = (const float*)d_in[18]; const float* be2 = (const float*)d_in[19];
    const float* W3  = (const float*)d_in[20]; const float* b3  = (const float*)d_in[21];
    const int*   ei  = (const int*)d_in[22];
    float* out = (float*)d_out;

    cudaFuncSetAttribute(conv_kernel, cudaFuncAttributeMaxDynamicSharedMemorySize, CONV_SMEM_BYTES);
    cudaFuncSetAttribute(mlp_kernel,  cudaFuncAttributeMaxDynamicSharedMemorySize, MLP_SMEM_BYTES);

    prep_kernel<<<179, 256>>>(ei, ew, W1, W2);
    conv_kernel<<<BATCH, 256, CONV_SMEM_BYTES>>>(state, pos, Wq, bq, Wk, bk, Wv, bv, We, Wsk, bsk);
    mlp_kernel<<<NROWS / 128, 512, MLP_SMEM_BYTES>>>(b1, g1, be1, b2, g2, be2, W3, b3);
    final_kernel<<<BATCH, 128>>>(out);
}

// round 7
// speedup vs baseline: 1.5830x; 1.2647x over previous
#include <cuda_runtime.h>
#include <cstdint>

typedef unsigned long long ull;

#define BATCH 256
#define NNODE 79
#define HID 256
#define NEDGE 3000
#define KP1 104                 // 97 inputs padded to 104 (13 panels of 8)
#define NROWS (BATCH*NNODE)     // 20224
#define MROWS 64                // rows per MLP CTA
#define NCH 24
#define CHSZ 125
#define NCELL (NNODE*NCH)       // 1896

// ---------------- device scratch ----------------
__device__ int   g_srcp[NEDGE];
__device__ int   g_dstp[NEDGE];
__device__ float g_ewp[NEDGE];
__device__ int   g_rowptr[NNODE + 1];
__device__ float g_W1U[KP1 * HID];       // k-major
__device__ float g_W2U[HID * HID];
__device__ float g_hin[(size_t)NROWS * KP1];
__device__ float g_conc[NROWS];

__device__ __forceinline__ float wredsum(float v) {
    #pragma unroll
    for (int o = 16; o; o >>= 1) v += __shfl_xor_sync(0xffffffffu, v, o);
    return v;
}
__device__ __forceinline__ float wredmax(float v) {
    #pragma unroll
    for (int o = 16; o; o >>= 1) v = fmaxf(v, __shfl_xor_sync(0xffffffffu, v, o));
    return v;
}

// ---- packed fp32x2 helpers ----
__device__ __forceinline__ ull dup2(float v) {
    ull r; asm("mov.b64 %0,{%1,%1};" : "=l"(r) : "f"(v)); return r;
}
__device__ __forceinline__ ull pk2(float a, float b) {
    ull r; asm("mov.b64 %0,{%1,%2};" : "=l"(r) : "f"(a), "f"(b)); return r;
}
__device__ __forceinline__ ull f2fma(ull a, ull b, ull c) {
    ull d; asm("fma.rn.f32x2 %0,%1,%2,%3;" : "=l"(d) : "l"(a), "l"(b), "l"(c)); return d;
}
__device__ __forceinline__ void up2(ull v, float& lo, float& hi) {
    asm("mov.b64 {%0,%1},%2;" : "=f"(lo), "=f"(hi) : "l"(v));
}
__device__ __forceinline__ void cpasync16(uint32_t saddr, const float* g) {
    asm volatile("cp.async.ca.shared.global [%0], [%1], 16;" :: "r"(saddr), "l"(g));
}

// ---------------- prep 1/3: CSR sort of edges by dst ----------------
__global__ __launch_bounds__(256) void prep_sort(const int* __restrict__ ei,
                                                 const float* __restrict__ ew) {
    __shared__ int dsts[NEDGE];
    __shared__ int cell[NCELL];
    __shared__ int wsum[8];
    int tid = threadIdx.x, lane = tid & 31, w = tid >> 5;
    for (int e = tid; e < NEDGE; e += 256) dsts[e] = ei[NEDGE + e];
    for (int c = tid; c < NCELL; c += 256) cell[c] = 0;
    __syncthreads();
    for (int e = tid; e < NEDGE; e += 256)
        atomicAdd(&cell[dsts[e] * NCH + e / CHSZ], 1);   // int atomics: deterministic
    __syncthreads();
    int base = tid * 8, loc[8], s = 0;
    #pragma unroll
    for (int j = 0; j < 8; j++) {
        int v = (base + j < NCELL) ? cell[base + j] : 0;
        loc[j] = s; s += v;
    }
    int x = s;
    #pragma unroll
    for (int o = 1; o < 32; o <<= 1) {
        int t = __shfl_up_sync(0xffffffffu, x, o);
        if (lane >= o) x += t;
    }
    if (lane == 31) wsum[w] = x;
    int exw = x - s;
    __syncthreads();
    if (tid == 0) {
        int a = 0;
        for (int i = 0; i < 8; i++) { int t = wsum[i]; wsum[i] = a; a += t; }
    }
    __syncthreads();
    int off = wsum[w] + exw;
    #pragma unroll
    for (int j = 0; j < 8; j++) if (base + j < NCELL) cell[base + j] = off + loc[j];
    __syncthreads();
    if (tid < NNODE) g_rowptr[tid] = cell[tid * NCH];
    if (tid == 0) g_rowptr[NNODE] = NEDGE;
    for (int e = tid; e < NEDGE; e += 256) {
        int d = dsts[e];
        int ch = e / CHSZ, b0 = ch * CHSZ;
        int rank = 0;
        for (int e2 = b0; e2 < e; e2++) rank += (dsts[e2] == d);
        int pos = cell[d * NCH + ch] + rank;
        g_dstp[pos] = d; g_srcp[pos] = ei[e]; g_ewp[pos] = ew[e];
    }
}

// ---------------- prep 2/3 + 3/3: weight transposes ----------------
__global__ __launch_bounds__(256) void prep_w1(const float* __restrict__ W1) {
    int t = blockIdx.x * 256 + threadIdx.x;
    if (t < KP1 * HID) {
        int k = t >> 8, j = t & 255;
        g_W1U[t] = (k < 97) ? W1[j * 97 + k] : 0.f;
    }
}
__global__ __launch_bounds__(256) void prep_w2(const float* __restrict__ W2) {
    int t = blockIdx.x * 256 + threadIdx.x;
    int k = t >> 8, j = t & 255;
    g_W2U[t] = W2[j * HID + k];
}

// ---------------- conv: one CTA per batch; 2 CTAs/SM (106.8 KB smem) ----------------
#define CONV_SMEM_FLOATS (2640 + 2*2080 + 3*5056 + 3000 + 80 + 64 + 4 + 80 + 1500)
#define CONV_SMEM_BYTES  (CONV_SMEM_FLOATS * 4)

__global__ __launch_bounds__(256, 2) void conv_kernel(
    const float* __restrict__ state, const float* __restrict__ pos,
    const float* __restrict__ Wq, const float* __restrict__ bq,
    const float* __restrict__ Wk, const float* __restrict__ bk,
    const float* __restrict__ Wv, const float* __restrict__ bv,
    const float* __restrict__ We,
    const float* __restrict__ Wsk, const float* __restrict__ bsk) {
    extern __shared__ float sm[];
    float* xs  = sm;              // 80*33
    float* WA  = xs + 2640;       // 32*65 k-major
    float* WB  = WA + 2080;
    float* qs  = WB + 2080;       // 79*64
    float* ks  = qs + 5056;
    float* vs  = ks + 5056;
    float* alp = vs + 5056;       // 3000
    float* qWe = alp + 3000;      // 80
    float* wes = qWe + 80;        // 64
    float* tot = wes + 64;        // 4
    int*   rps = (int*)(tot + 4); // 80
    short* srcp_s = (short*)(rps + 80);   // 3000 int16

    int b = blockIdx.x, tid = threadIdx.x, lane = tid & 31, w = tid >> 5;

    // phase 1: stage x, Wq/Wk, src indices, rowptr, We
    for (int idx = tid; idx < 80 * 32; idx += 256) {
        int i = idx >> 5, k = idx & 31;
        float v = 0.f;
        if (i < NNODE) v = (k < 26) ? state[((size_t)b * NNODE + i) * 26 + k]
                                    : pos[i * 6 + (k - 26)];
        xs[i * 33 + k] = v;
    }
    for (int idx = tid; idx < 64 * 32; idx += 256) {
        int d = idx >> 5, k = idx & 31;
        WA[k * 65 + d] = Wq[idx];
        WB[k * 65 + d] = Wk[idx];
    }
    for (int e = tid; e < NEDGE; e += 256) srcp_s[e] = (short)g_srcp[e];
    if (tid <= NNODE) rps[tid] = g_rowptr[tid];
    if (tid < 64) wes[tid] = We[tid];
    __syncthreads();

    // phase 2: total agents + GEMM A (q,k)
    if (tid == 0) {
        float t = 0.f;
        for (int i = 0; i < NNODE; i++) t += xs[i * 33 + 1];
        tot[0] = t;
    }
    #pragma unroll 1
    for (int it = 0; it < 5; it++) {
        int item = tid + it * 256;
        int d = item & 63, i0 = (item >> 6) << 2;
        float aq[4] = {0,0,0,0}, ak[4] = {0,0,0,0};
        #pragma unroll 8
        for (int k = 0; k < 32; k++) {
            float wq = WA[k * 65 + d], wk = WB[k * 65 + d];
            #pragma unroll
            for (int n = 0; n < 4; n++) {
                float xv = xs[(i0 + n) * 33 + k];
                aq[n] += xv * wq; ak[n] += xv * wk;
            }
        }
        float bqv = __ldg(bq + d), bkv = __ldg(bk + d);
        #pragma unroll
        for (int n = 0; n < 4; n++) {
            if (i0 + n < NNODE) {
                qs[(i0 + n) * 64 + d] = aq[n] + bqv;
                ks[(i0 + n) * 64 + d] = ak[n] + bkv;
            }
        }
    }
    __syncthreads();

    // phase 3: qWe, restage Wv/Wsk, hin tail
    if (tid < NNODE) {
        float a = 0.f;
        const float* qr = qs + tid * 64;
        #pragma unroll 8
        for (int d = 0; d < 64; d++) a += qr[d] * wes[d];
        qWe[tid] = a;
    }
    for (int idx = tid; idx < 64 * 32; idx += 256) {
        int d = idx >> 5, k = idx & 31;
        WA[k * 65 + d] = Wv[idx];
        WB[k * 65 + d] = Wsk[idx];
    }
    for (int idx = tid; idx < NNODE * 40; idx += 256) {
        int i = idx / 40, c = idx - i * 40;
        size_t r = (size_t)b * NNODE + i;
        float v;
        if (c == 0) v = tot[0];
        else if (c <= 32) v = xs[i * 33 + (c - 1)];
        else v = 0.f;
        g_hin[r * KP1 + 64 + c] = v;
    }
    __syncthreads();

    // phase 4: GEMM B (v -> smem, skip -> g_hin raw)
    #pragma unroll 1
    for (int it = 0; it < 5; it++) {
        int item = tid + it * 256;
        int d = item & 63, i0 = (item >> 6) << 2;
        float av[4] = {0,0,0,0}, as[4] = {0,0,0,0};
        #pragma unroll 8
        for (int k = 0; k < 32; k++) {
            float wv = WA[k * 65 + d], ws = WB[k * 65 + d];
            #pragma unroll
            for (int n = 0; n < 4; n++) {
                float xv = xs[(i0 + n) * 33 + k];
                av[n] += xv * wv; as[n] += xv * ws;
            }
        }
        float bvv = __ldg(bv + d), bsv = __ldg(bsk + d);
        #pragma unroll
        for (int n = 0; n < 4; n++) {
            if (i0 + n < NNODE) {
                vs[(i0 + n) * 64 + d] = av[n] + bvv;
                g_hin[((size_t)b * NNODE + i0 + n) * KP1 + d] = as[n] + bsv;
            }
        }
    }

    // phase 5: alpha, node-ordered — warp per node, 8-lane group per edge,
    // q row hoisted into registers, uniform trip count (safe shuffles)
    {
        int g = lane >> 3, li = lane & 7;
        for (int i = w; i < NNODE; i += 8) {
            int s0 = rps[i], e1 = rps[i + 1];
            const float4* qr = (const float4*)(qs + i * 64 + li * 8);
            float4 q0 = qr[0], q1 = qr[1];
            float qwei = qWe[i];
            #pragma unroll 1
            for (int eb = s0; eb < e1; eb += 4) {
                int e = eb + g;
                bool valid = e < e1;
                int ec = valid ? e : e1 - 1;
                int ss = srcp_s[ec];
                float ewv = __ldg(g_ewp + ec);
                const float4* kr = (const float4*)(ks + ss * 64 + li * 8);
                float4 k0 = kr[0], k1 = kr[1];
                float p = q0.x*k0.x + q0.y*k0.y + q0.z*k0.z + q0.w*k0.w
                        + q1.x*k1.x + q1.y*k1.y + q1.z*k1.z + q1.w*k1.w;
                p += __shfl_xor_sync(0xffffffffu, p, 1);
                p += __shfl_xor_sync(0xffffffffu, p, 2);
                p += __shfl_xor_sync(0xffffffffu, p, 4);
                if (li == 0 && valid) alp[e] = 0.125f * (p + ewv * qwei);
            }
        }
    }
    __syncthreads();

    // phase 6: softmax + aggregation (warp per node)
    float we0 = wes[lane], we1 = wes[lane + 32];
    for (int i = w; i < NNODE; i += 8) {
        int s0 = rps[i], e1 = rps[i + 1];
        float a0 = 0.f, a1 = 0.f;
        if (e1 > s0) {
            float m = -1e30f;
            for (int e = s0 + lane; e < e1; e += 32) m = fmaxf(m, alp[e]);
            m = wredmax(m);
            float den = 0.f, sew = 0.f;
            for (int e = s0 + lane; e < e1; e += 32) {
                float ex = __expf(alp[e] - m);
                alp[e] = ex; den += ex; sew += ex * g_ewp[e];
            }
            den = wredsum(den); sew = wredsum(sew);
            float inv = 1.f / (den + 1e-16f);
            float b0 = 0.f, b1 = 0.f;
            int e = s0;
            #pragma unroll 1
            for (; e + 1 < e1; e += 2) {
                float w0 = alp[e], w1v = alp[e + 1];
                int sA = srcp_s[e], sB = srcp_s[e + 1];
                a0 += w0 * vs[sA * 64 + lane];
                a1 += w0 * vs[sA * 64 + lane + 32];
                b0 += w1v * vs[sB * 64 + lane];
                b1 += w1v * vs[sB * 64 + lane + 32];
            }
            if (e < e1) {
                float w0 = alp[e]; int sA = srcp_s[e];
                a0 += w0 * vs[sA * 64 + lane];
                a1 += w0 * vs[sA * 64 + lane + 32];
            }
            a0 = (a0 + b0 + sew * we0) * inv;
            a1 = (a1 + b1 + sew * we1) * inv;
        }
        size_t r = (size_t)b * NNODE + i;
        float s0v = g_hin[r * KP1 + lane];
        float s1v = g_hin[r * KP1 + lane + 32];
        g_hin[r * KP1 + lane]      = fmaxf(a0 + s0v, 0.f);
        g_hin[r * KP1 + lane + 32] = fmaxf(a1 + s1v, 0.f);
    }
}

// ---------------- MLP: f32x2, 64 rows/CTA, 256 threads, 2 CTAs/SM ----------------
// smem floats: xs 6656 | hb 16384 | wp 4096 | mu 64 | rsd 64 | w3 256 = 27520 (110 KB)
#define MLP_SMEM_FLOATS (6656 + 16384 + 4096 + 64 + 64 + 256)
#define MLP_SMEM_BYTES  (MLP_SMEM_FLOATS * 4)

template<int K>
__device__ __forceinline__ void gemm_panels(const float* __restrict__ Wg,
                                            const float* __restrict__ xsrc,
                                            float* __restrict__ wp, uint32_t wp_s32,
                                            float4 bvv, ull (&acc)[4][8],
                                            int c4, int pbase, int tid) {
    const int NP = K / 8;
    cpasync16(wp_s32 + tid * 16, Wg + tid * 4);
    cpasync16(wp_s32 + 4096 + tid * 16, Wg + 1024 + tid * 4);
    asm volatile("cp.async.commit_group;");
    #pragma unroll
    for (int rp = 0; rp < 8; rp++) {
        acc[0][rp] = dup2(bvv.x); acc[1][rp] = dup2(bvv.y);
        acc[2][rp] = dup2(bvv.z); acc[3][rp] = dup2(bvv.w);
    }
    const float* xb = xsrc + (size_t)pbase * K * 2;
    #pragma unroll 1
    for (int p = 0; p < NP; p++) {
        if (p + 1 < NP) {
            uint32_t dst = wp_s32 + ((p + 1) & 1) * 8192;
            cpasync16(dst + tid * 16, Wg + (p + 1) * 2048 + tid * 4);
            cpasync16(dst + 4096 + tid * 16, Wg + (p + 1) * 2048 + 1024 + tid * 4);
            asm volatile("cp.async.commit_group;");
            asm volatile("cp.async.wait_group 1;");
        } else {
            asm volatile("cp.async.wait_group 0;");
        }
        __syncthreads();
        const float* wb = wp + (p & 1) * 2048;
        #pragma unroll
        for (int kk2 = 0; kk2 < 4; kk2++) {
            int kl = kk2 * 2;
            float4 wa = *(const float4*)(wb + kl * 256 + 4 * c4);
            float4 wc = *(const float4*)(wb + (kl + 1) * 256 + 4 * c4);
            ull a0 = dup2(wa.x), a1 = dup2(wa.y), a2 = dup2(wa.z), a3 = dup2(wa.w);
            ull c0 = dup2(wc.x), c1 = dup2(wc.y), c2 = dup2(wc.z), c3 = dup2(wc.w);
            int kg = p * 8 + kl;
            #pragma unroll
            for (int rp = 0; rp < 8; rp++) {
                ulonglong2 xv = *(const ulonglong2*)(xb + ((size_t)rp * K + kg) * 2);
                acc[0][rp] = f2fma(xv.x, a0, acc[0][rp]);
                acc[1][rp] = f2fma(xv.x, a1, acc[1][rp]);
                acc[2][rp] = f2fma(xv.x, a2, acc[2][rp]);
                acc[3][rp] = f2fma(xv.x, a3, acc[3][rp]);
                acc[0][rp] = f2fma(xv.y, c0, acc[0][rp]);
                acc[1][rp] = f2fma(xv.y, c1, acc[1][rp]);
                acc[2][rp] = f2fma(xv.y, c2, acc[2][rp]);
                acc[3][rp] = f2fma(xv.y, c3, acc[3][rp]);
            }
        }
        __syncthreads();
    }
}

__global__ __launch_bounds__(256, 2) void mlp_kernel(
    const float* __restrict__ b1, const float* __restrict__ g1, const float* __restrict__ be1,
    const float* __restrict__ b2, const float* __restrict__ g2, const float* __restrict__ be2,
    const float* __restrict__ W3, const float* __restrict__ b3) {
    extern __shared__ float sm[];
    float* xs  = sm;                  // 32 pr x 104 k x 2
    float* hb  = xs + 6656;           // 32 pr x 256 ch x 2
    float* wp  = hb + 16384;          // 2 x 8 x 256 weight panels
    float* mu  = wp + 4096;           // 64
    float* rsd = mu + 64;             // 64
    float* w3s = rsd + 64;            // 256
    ull* hbp = (ull*)hb;
    uint32_t wp_s32 = (uint32_t)__cvta_generic_to_shared(wp);
    int tid = threadIdx.x, lane = tid & 31, w = tid >> 5;
    int c4 = tid & 63, pbase = (tid >> 6) * 8;
    size_t row0 = (size_t)blockIdx.x * MROWS;

    {
        const float4* src4 = (const float4*)(g_hin + row0 * KP1);
        for (int i = tid; i < MROWS * 26; i += 256) {
            int r = i / 26, q = i - r * 26;
            float4 f = src4[i];
            float* d = xs + ((r >> 1) * KP1 + 4 * q) * 2 + (r & 1);
            d[0] = f.x; d[2] = f.y; d[4] = f.z; d[6] = f.w;
        }
    }
    w3s[tid] = W3[tid];
    __syncthreads();

    ull acc[4][8];
    // ---- layer 1 ----
    gemm_panels<KP1>(g_W1U, xs, wp, wp_s32, ((const float4*)b1)[c4], acc, c4, pbase, tid);
    #pragma unroll
    for (int rp = 0; rp < 8; rp++)
        #pragma unroll
        for (int c = 0; c < 4; c++)
            hbp[(size_t)(pbase + rp) * HID + 4 * c4 + c] = acc[c][rp];
    __syncthreads();
    for (int r = w; r < MROWS; r += 8) {
        int pr = r >> 1, par = r & 1;
        float s = 0.f, s2 = 0.f;
        #pragma unroll
        for (int t = 0; t < 8; t++) {
            float v = hb[((size_t)pr * HID + lane + t * 32) * 2 + par];
            s += v; s2 += v * v;
        }
        s = wredsum(s); s2 = wredsum(s2);
        if (lane == 0) {
            float m = s * (1.f / HID);
            mu[r] = m;
            rsd[r] = rsqrtf(s2 * (1.f / HID) - m * m + 1e-5f);
        }
    }
    __syncthreads();
    {
        float4 gv = ((const float4*)g1)[c4], bev = ((const float4*)be1)[c4];
        float ga[4] = {gv.x, gv.y, gv.z, gv.w}, ba[4] = {bev.x, bev.y, bev.z, bev.w};
        #pragma unroll
        for (int rp = 0; rp < 8; rp++) {
            int pr = pbase + rp;
            float m0 = mu[2*pr], m1 = mu[2*pr+1], r0 = rsd[2*pr], r1 = rsd[2*pr+1];
            #pragma unroll
            for (int c = 0; c < 4; c++) {
                float lo, hi; up2(acc[c][rp], lo, hi);
                float h0 = (lo - m0) * r0 * ga[c] + ba[c];
                float h1 = (hi - m1) * r1 * ga[c] + ba[c];
                h0 = h0 > 0.f ? h0 : 0.01f * h0;
                h1 = h1 > 0.f ? h1 : 0.01f * h1;
                hbp[(size_t)pr * HID + 4 * c4 + c] = pk2(h0, h1);
            }
        }
    }
    __syncthreads();

    // ---- layer 2 ----
    gemm_panels<HID>(g_W2U, hb, wp, wp_s32, ((const float4*)b2)[c4], acc, c4, pbase, tid);
    #pragma unroll
    for (int rp = 0; rp < 8; rp++)
        #pragma unroll
        for (int c = 0; c < 4; c++)
            hbp[(size_t)(pbase + rp) * HID + 4 * c4 + c] = acc[c][rp];
    __syncthreads();
    for (int r = w; r < MROWS; r += 8) {
        int pr = r >> 1, par = r & 1;
        float s = 0.f, s2 = 0.f;
        #pragma unroll
        for (int t = 0; t < 8; t++) {
            float v = hb[((size_t)pr * HID + lane + t * 32) * 2 + par];
            s += v; s2 += v * v;
        }
        s = wredsum(s); s2 = wredsum(s2);
        if (lane == 0) {
            float m = s * (1.f / HID);
            mu[r] = m;
            rsd[r] = rsqrtf(s2 * (1.f / HID) - m * m + 1e-5f);
        }
    }
    __syncthreads();
    {
        float4 gv = ((const float4*)g2)[c4], bev = ((const float4*)be2)[c4];
        float ga[4] = {gv.x, gv.y, gv.z, gv.w}, ba[4] = {bev.x, bev.y, bev.z, bev.w};
        #pragma unroll
        for (int rp = 0; rp < 8; rp++) {
            int pr = pbase + rp;
            float m0 = mu[2*pr], m1 = mu[2*pr+1], r0 = rsd[2*pr], r1 = rsd[2*pr+1];
            #pragma unroll
            for (int c = 0; c < 4; c++) {
                float lo, hi; up2(acc[c][rp], lo, hi);
                float w3c = w3s[4 * c4 + c];
                float h0 = (lo - m0) * r0 * ga[c] + ba[c];
                float h1 = (hi - m1) * r1 * ga[c] + ba[c];
                h0 = h0 > 0.f ? h0 : 0.01f * h0;
                h1 = h1 > 0.f ? h1 : 0.01f * h1;
                hbp[(size_t)pr * HID + 4 * c4 + c] = pk2(h0 * w3c, h1 * w3c);
            }
        }
    }
    __syncthreads();
    float b3v = b3[0];
    for (int r = w; r < MROWS; r += 8) {
        int pr = r >> 1, par = r & 1;
        float s = 0.f;
        #pragma unroll
        for (int t = 0; t < 8; t++)
            s += hb[((size_t)pr * HID + lane + t * 32) * 2 + par];
        s = wredsum(s);
        if (lane == 0) {
            float yv = s + b3v;
            g_conc[row0 + r] = (yv > 20.f) ? yv : log1pf(expf(yv));
        }
    }
}

// ---------------- final normalize per batch ----------------
__global__ __launch_bounds__(128) void final_kernel(float* __restrict__ out) {
    __shared__ float sb[4];
    int b = blockIdx.x, tid = threadIdx.x, lane = tid & 31, w = tid >> 5;
    float v = (tid < NNODE) ? g_conc[b * NNODE + tid] : 0.f;
    float s = v;
    #pragma unroll
    for (int o = 16; o; o >>= 1) s += __shfl_xor_sync(0xffffffffu, s, o);
    if (lane == 0) sb[w] = s;
    __syncthreads();
    float tt = sb[0] + sb[1] + sb[2] + sb[3];
    if (tid < NNODE) out[b * NNODE + tid] = v / (tt + 1e-20f);
}

// ---------------- launch ----------------
extern "C" void kernel_launch(void* const* d_in, const int* in_sizes, int n_in,
                              void* d_out, int out_size) {
    const float* state = (const float*)d_in[0];
    const float* pos   = (const float*)d_in[1];
    const float* ew    = (const float*)d_in[2];
    const float* Wq  = (const float*)d_in[3];  const float* bq  = (const float*)d_in[4];
    const float* Wk  = (const float*)d_in[5];  const float* bk  = (const float*)d_in[6];
    const float* Wv  = (const float*)d_in[7];  const float* bv  = (const float*)d_in[8];
    const float* We  = (const float*)d_in[9];
    const float* Wsk = (const float*)d_in[10]; const float* bsk = (const float*)d_in[11];
    const float* W1  = (const float*)d_in[12]; const float* b1  = (const float*)d_in[13];
    const float* g1  = (const float*)d_in[14]; const float* be1 = (const float*)d_in[15];
    const float* W2  = (const float*)d_in[16]; const float* b2  = (const float*)d_in[17];
    const float* g2  = (const float*)d_in[18]; const float* be2 = (const float*)d_in[19];
    const float* W3  = (const float*)d_in[20]; const float* b3  = (const float*)d_in[21];
    const int*   ei  = (const int*)d_in[22];
    float* out = (float*)d_out;

    cudaFuncSetAttribute(conv_kernel, cudaFuncAttributeMaxDynamicSharedMemorySize, CONV_SMEM_BYTES);
    cudaFuncSetAttribute(mlp_kernel,  cudaFuncAttributeMaxDynamicSharedMemorySize, MLP_SMEM_BYTES);

    prep_sort<<<1, 256>>>(ei, ew);                         // launch 1
    prep_w1<<<(KP1 * HID + 255) / 256, 256>>>(W1);         // launch 2
    prep_w2<<<HID * HID / 256, 256>>>(W2);                 // launch 3
    conv_kernel<<<BATCH, 256, CONV_SMEM_BYTES>>>(          // launch 4 (profiled)
        state, pos, Wq, bq, Wk, bk, Wv, bv, We, Wsk, bsk);
    mlp_kernel<<<NROWS / MROWS, 256, MLP_SMEM_BYTES>>>(b1, g1, be1, b2, g2, be2, W3, b3);
    final_kernel<<<BATCH, 128>>>(out);
}

// round 8
// speedup vs baseline: 1.5939x; 1.0069x over previous
#include <cuda_runtime.h>
#include <cstdint>

typedef unsigned long long ull;

#define BATCH 256
#define NNODE 79
#define HID 256
#define NEDGE 3000
#define KP1 104
#define NROWS (BATCH*NNODE)     // 20224
#define MROWS 64
#define NCH 24
#define CHSZ 125
#define NCELL (NNODE*NCH)

// ---------------- device scratch ----------------
__device__ int   g_srcp[NEDGE];
__device__ float g_ewp[NEDGE];
__device__ int   g_rowptr[NNODE + 1];
__device__ float g_W4U[32 * 256];        // k-major stacked q|k|v|skip
__device__ float g_W1U[KP1 * HID];
__device__ float g_W2U[HID * HID];
__device__ float g_q[(size_t)NROWS * 64];
__device__ float g_k[(size_t)NROWS * 64];
__device__ float g_v[(size_t)NROWS * 64];
__device__ float g_hin[(size_t)NROWS * KP1];
__device__ float g_conc[NROWS];

__device__ __forceinline__ float wredsum(float v) {
    #pragma unroll
    for (int o = 16; o; o >>= 1) v += __shfl_xor_sync(0xffffffffu, v, o);
    return v;
}
__device__ __forceinline__ float wredmax(float v) {
    #pragma unroll
    for (int o = 16; o; o >>= 1) v = fmaxf(v, __shfl_xor_sync(0xffffffffu, v, o));
    return v;
}
__device__ __forceinline__ ull dup2(float v) {
    ull r; asm("mov.b64 %0,{%1,%1};" : "=l"(r) : "f"(v)); return r;
}
__device__ __forceinline__ ull pk2(float a, float b) {
    ull r; asm("mov.b64 %0,{%1,%2};" : "=l"(r) : "f"(a), "f"(b)); return r;
}
__device__ __forceinline__ ull f2fma(ull a, ull b, ull c) {
    ull d; asm("fma.rn.f32x2 %0,%1,%2,%3;" : "=l"(d) : "l"(a), "l"(b), "l"(c)); return d;
}
__device__ __forceinline__ void up2(ull v, float& lo, float& hi) {
    asm("mov.b64 {%0,%1},%2;" : "=f"(lo), "=f"(hi) : "l"(v));
}
__device__ __forceinline__ void cpasync16(uint32_t saddr, const float* g) {
    asm volatile("cp.async.ca.shared.global [%0], [%1], 16;" :: "r"(saddr), "l"(g));
}

// ---------------- prep: block0 = CSR sort; blocks 1.. = weight transposes ----------------
__global__ __launch_bounds__(256) void prep_kernel(
    const int* __restrict__ ei, const float* __restrict__ ew,
    const float* __restrict__ Wq, const float* __restrict__ Wk,
    const float* __restrict__ Wv, const float* __restrict__ Wsk,
    const float* __restrict__ W1, const float* __restrict__ W2) {
    int tid = threadIdx.x;
    if (blockIdx.x == 0) {
        __shared__ int dsts[NEDGE];
        __shared__ int cell[NCELL];
        __shared__ int wsum[8];
        int lane = tid & 31, w = tid >> 5;
        for (int e = tid; e < NEDGE; e += 256) dsts[e] = ei[NEDGE + e];
        for (int c = tid; c < NCELL; c += 256) cell[c] = 0;
        __syncthreads();
        for (int e = tid; e < NEDGE; e += 256)
            atomicAdd(&cell[dsts[e] * NCH + e / CHSZ], 1);
        __syncthreads();
        int base = tid * 8, loc[8], s = 0;
        #pragma unroll
        for (int j = 0; j < 8; j++) {
            int v = (base + j < NCELL) ? cell[base + j] : 0;
            loc[j] = s; s += v;
        }
        int x = s;
        #pragma unroll
        for (int o = 1; o < 32; o <<= 1) {
            int t = __shfl_up_sync(0xffffffffu, x, o);
            if (lane >= o) x += t;
        }
        if (lane == 31) wsum[w] = x;
        int exw = x - s;
        __syncthreads();
        if (tid == 0) {
            int a = 0;
            for (int i = 0; i < 8; i++) { int t = wsum[i]; wsum[i] = a; a += t; }
        }
        __syncthreads();
        int off = wsum[w] + exw;
        #pragma unroll
        for (int j = 0; j < 8; j++) if (base + j < NCELL) cell[base + j] = off + loc[j];
        __syncthreads();
        if (tid < NNODE) g_rowptr[tid] = cell[tid * NCH];
        if (tid == 0) g_rowptr[NNODE] = NEDGE;
        for (int e = tid; e < NEDGE; e += 256) {
            int d = dsts[e];
            int ch = e / CHSZ, b0 = ch * CHSZ;
            int rank = 0;
            for (int e2 = b0; e2 < e; e2++) rank += (dsts[e2] == d);
            int pos = cell[d * NCH + ch] + rank;
            g_srcp[pos] = ei[e]; g_ewp[pos] = ew[e];
        }
    } else {
        int gtid = (blockIdx.x - 1) * 256 + tid, gs = (gridDim.x - 1) * 256;
        for (int t = gtid; t < 32 * 256; t += gs) {
            int k = t >> 8, ch = t & 255;
            float v;
            if (ch < 64)       v = Wq[ch * 32 + k];
            else if (ch < 128) v = Wk[(ch - 64) * 32 + k];
            else if (ch < 192) v = Wv[(ch - 128) * 32 + k];
            else               v = Wsk[(ch - 192) * 32 + k];
            g_W4U[t] = v;
        }
        for (int t = gtid; t < KP1 * HID; t += gs) {
            int k = t >> 8, j = t & 255;
            g_W1U[t] = (k < 97) ? W1[j * 97 + k] : 0.f;
        }
        for (int t = gtid; t < HID * HID; t += gs) {
            int k = t >> 8, j = t & 255;
            g_W2U[t] = W2[j * HID + k];
        }
    }
}

// ---------------- shared f32x2 GEMM engine (k-panel pipelined) ----------------
template<int K>
__device__ __forceinline__ void gemm_panels(const float* __restrict__ Wg,
                                            const float* __restrict__ xsrc,
                                            float* __restrict__ wp, uint32_t wp_s32,
                                            float4 bvv, ull (&acc)[4][8],
                                            int c4, int pbase, int tid) {
    const int NP = K / 8;
    cpasync16(wp_s32 + tid * 16, Wg + tid * 4);
    cpasync16(wp_s32 + 4096 + tid * 16, Wg + 1024 + tid * 4);
    asm volatile("cp.async.commit_group;");
    #pragma unroll
    for (int rp = 0; rp < 8; rp++) {
        acc[0][rp] = dup2(bvv.x); acc[1][rp] = dup2(bvv.y);
        acc[2][rp] = dup2(bvv.z); acc[3][rp] = dup2(bvv.w);
    }
    const float* xb = xsrc + (size_t)pbase * K * 2;
    #pragma unroll 1
    for (int p = 0; p < NP; p++) {
        if (p + 1 < NP) {
            uint32_t dst = wp_s32 + ((p + 1) & 1) * 8192;
            cpasync16(dst + tid * 16, Wg + (p + 1) * 2048 + tid * 4);
            cpasync16(dst + 4096 + tid * 16, Wg + (p + 1) * 2048 + 1024 + tid * 4);
            asm volatile("cp.async.commit_group;");
            asm volatile("cp.async.wait_group 1;");
        } else {
            asm volatile("cp.async.wait_group 0;");
        }
        __syncthreads();
        const float* wb = wp + (p & 1) * 2048;
        #pragma unroll
        for (int kk2 = 0; kk2 < 4; kk2++) {
            int kl = kk2 * 2;
            float4 wa = *(const float4*)(wb + kl * 256 + 4 * c4);
            float4 wc = *(const float4*)(wb + (kl + 1) * 256 + 4 * c4);
            ull a0 = dup2(wa.x), a1 = dup2(wa.y), a2 = dup2(wa.z), a3 = dup2(wa.w);
            ull c0 = dup2(wc.x), c1 = dup2(wc.y), c2 = dup2(wc.z), c3 = dup2(wc.w);
            int kg = p * 8 + kl;
            #pragma unroll
            for (int rp = 0; rp < 8; rp++) {
                ulonglong2 xv = *(const ulonglong2*)(xb + ((size_t)rp * K + kg) * 2);
                acc[0][rp] = f2fma(xv.x, a0, acc[0][rp]);
                acc[1][rp] = f2fma(xv.x, a1, acc[1][rp]);
                acc[2][rp] = f2fma(xv.x, a2, acc[2][rp]);
                acc[3][rp] = f2fma(xv.x, a3, acc[3][rp]);
                acc[0][rp] = f2fma(xv.y, c0, acc[0][rp]);
                acc[1][rp] = f2fma(xv.y, c1, acc[1][rp]);
                acc[2][rp] = f2fma(xv.y, c2, acc[2][rp]);
                acc[3][rp] = f2fma(xv.y, c3, acc[3][rp]);
            }
        }
        __syncthreads();
    }
}

// ---------------- qkvs: batched GEMM X[20224x32] @ W4[32x256] ----------------
// smem floats: xs 2048 | hb 16384 | wp 4096 | bias 256
#define QKVS_SMEM_FLOATS (2048 + 16384 + 4096 + 256)
#define QKVS_SMEM_BYTES  (QKVS_SMEM_FLOATS * 4)

__global__ __launch_bounds__(256, 2) void qkvs_kernel(
    const float* __restrict__ state, const float* __restrict__ pos,
    const float* __restrict__ bq, const float* __restrict__ bk,
    const float* __restrict__ bv, const float* __restrict__ bsk) {
    extern __shared__ float sm[];
    float* xs   = sm;              // 32 pr x 32 k x 2
    float* hb   = xs + 2048;       // 32 pr x 256 ch x 2
    float* wp   = hb + 16384;      // 2 x 2048 weight panels
    float* bias = wp + 4096;       // 256
    ull* hbp = (ull*)hb;
    uint32_t wp_s32 = (uint32_t)__cvta_generic_to_shared(wp);
    int tid = threadIdx.x;
    int c4 = tid & 63, pbase = (tid >> 6) * 8;
    size_t row0 = (size_t)blockIdx.x * MROWS;

    // stage x pair-interleaved: x = concat(state[26], pos[6])
    for (int idx = tid; idx < MROWS * 32; idx += 256) {
        int r = idx >> 5, k = idx & 31;
        size_t g = row0 + r;
        int node = (int)(g % NNODE);
        float v = (k < 26) ? state[g * 26 + k] : pos[node * 6 + (k - 26)];
        xs[((r >> 1) * 32 + k) * 2 + (r & 1)] = v;
    }
    {
        int ch = tid;
        float v = (ch < 64) ? bq[ch] : (ch < 128) ? bk[ch - 64]
                : (ch < 192) ? bv[ch - 128] : bsk[ch - 192];
        bias[ch] = v;
    }
    __syncthreads();

    ull acc[4][8];
    gemm_panels<32>(g_W4U, xs, wp, wp_s32, ((const float4*)bias)[c4], acc, c4, pbase, tid);
    #pragma unroll
    for (int rp = 0; rp < 8; rp++)
        #pragma unroll
        for (int c = 0; c < 4; c++)
            hbp[(size_t)(pbase + rp) * 256 + 4 * c4 + c] = acc[c][rp];
    __syncthreads();

    // write out: q,k,v -> global [row*64], skip -> g_hin[row*104 + 0..63]
    for (int i = tid; i < MROWS * 64; i += 256) {
        int r = i >> 6, d = i & 63;
        int pr = r >> 1, par = r & 1;
        size_t g = row0 + r;
        g_q[g * 64 + d]       = hb[((size_t)(pr * 256) + d) * 2 + par];
        g_k[g * 64 + d]       = hb[((size_t)(pr * 256) + 64 + d) * 2 + par];
        g_v[g * 64 + d]       = hb[((size_t)(pr * 256) + 128 + d) * 2 + par];
        g_hin[g * KP1 + d]    = hb[((size_t)(pr * 256) + 192 + d) * 2 + par];
    }
}

// ---------------- edge: per-batch attention (no GEMMs) ----------------
// floats: qs/ks/vs 3*5372 | alp 3000 | qWe 80 | wes 64 | tot 4 | rps 80 | sx 80 | srcp 1500
#define EDGE_SMEM_FLOATS (3*5372 + 3000 + 80 + 64 + 4 + 80 + 80 + 1500)
#define EDGE_SMEM_BYTES  (EDGE_SMEM_FLOATS * 4)

__global__ __launch_bounds__(256, 2) void edge_kernel(
    const float* __restrict__ state, const float* __restrict__ pos,
    const float* __restrict__ We) {
    extern __shared__ float sm[];
    float* qs  = sm;               // 79 x 68
    float* ks  = qs + 5372;
    float* vs  = ks + 5372;
    float* alp = vs + 5372;        // 3000
    float* qWe = alp + 3000;       // 80
    float* wes = qWe + 80;         // 64
    float* tot = wes + 64;         // 4
    int*   rps = (int*)(tot + 4);  // 80
    float* sx  = (float*)(rps + 80);      // 80
    short* srcp_s = (short*)(sx + 80);    // 3000 int16

    int b = blockIdx.x, tid = threadIdx.x, lane = tid & 31, w = tid >> 5;
    size_t base = (size_t)b * NNODE;

    // stage q,k,v (pad-68 rows), indices, misc
    for (int idx = tid; idx < NNODE * 16; idx += 256) {
        int row = idx >> 4, f4 = idx & 15;
        float4 qv = __ldg(((const float4*)(g_q + (base + row) * 64)) + f4);
        float4 kv = __ldg(((const float4*)(g_k + (base + row) * 64)) + f4);
        float4 vv = __ldg(((const float4*)(g_v + (base + row) * 64)) + f4);
        *(float4*)(qs + row * 68 + f4 * 4) = qv;
        *(float4*)(ks + row * 68 + f4 * 4) = kv;
        *(float4*)(vs + row * 68 + f4 * 4) = vv;
    }
    for (int e = tid; e < NEDGE; e += 256) srcp_s[e] = (short)g_srcp[e];
    if (tid <= NNODE) rps[tid] = g_rowptr[tid];
    if (tid < 64) wes[tid] = We[tid];
    if (tid < NNODE) sx[tid] = __ldg(state + (base + tid) * 26 + 1);
    __syncthreads();

    // tot (warp 0) + qWe (tid<79)
    if (w == 0) {
        float s = 0.f;
        for (int j = lane; j < NNODE; j += 32) s += sx[j];
        s = wredsum(s);
        if (lane == 0) tot[0] = s;
    }
    if (tid < NNODE) {
        float a = 0.f;
        const float* qr = qs + tid * 68;
        #pragma unroll 8
        for (int d = 0; d < 64; d++) a += qr[d] * wes[d];
        qWe[tid] = a;
    }
    __syncthreads();

    // alpha: node-ordered, warp per node, 8-lane group per edge
    {
        int g = lane >> 3, li = lane & 7;
        for (int i = w; i < NNODE; i += 8) {
            int s0 = rps[i], e1 = rps[i + 1];
            const float4* qr = (const float4*)(qs + i * 68 + li * 8);
            float4 q0 = qr[0], q1 = qr[1];
            float qwei = qWe[i];
            #pragma unroll 1
            for (int eb = s0; eb < e1; eb += 4) {
                int e = eb + g;
                bool valid = e < e1;
                int ec = valid ? e : e1 - 1;
                int ss = srcp_s[ec];
                float ewv = __ldg(g_ewp + ec);
                const float4* kr = (const float4*)(ks + ss * 68 + li * 8);
                float4 k0 = kr[0], k1 = kr[1];
                float p = q0.x*k0.x + q0.y*k0.y + q0.z*k0.z + q0.w*k0.w
                        + q1.x*k1.x + q1.y*k1.y + q1.z*k1.z + q1.w*k1.w;
                p += __shfl_xor_sync(0xffffffffu, p, 1);
                p += __shfl_xor_sync(0xffffffffu, p, 2);
                p += __shfl_xor_sync(0xffffffffu, p, 4);
                if (li == 0 && valid) alp[e] = 0.125f * (p + ewv * qwei);
            }
        }
    }
    // hin tail: col64=tot, 65..90=state, 91..96=pos, 97..103=0
    for (int idx = tid; idx < NNODE * 40; idx += 256) {
        int i = idx / 40, c = idx - i * 40;
        float v;
        if (c == 0) v = tot[0];
        else if (c <= 26) v = __ldg(state + (base + i) * 26 + (c - 1));
        else if (c <= 32) v = __ldg(pos + i * 6 + (c - 27));
        else v = 0.f;
        g_hin[(base + i) * KP1 + 64 + c] = v;
    }
    __syncthreads();

    // softmax + aggregation (warp per node)
    float we0 = wes[lane], we1 = wes[lane + 32];
    for (int i = w; i < NNODE; i += 8) {
        int s0 = rps[i], e1 = rps[i + 1];
        float a0 = 0.f, a1 = 0.f;
        if (e1 > s0) {
            float m = -1e30f;
            for (int e = s0 + lane; e < e1; e += 32) m = fmaxf(m, alp[e]);
            m = wredmax(m);
            float den = 0.f, sew = 0.f;
            for (int e = s0 + lane; e < e1; e += 32) {
                float ex = __expf(alp[e] - m);
                alp[e] = ex; den += ex; sew += ex * __ldg(g_ewp + e);
            }
            den = wredsum(den); sew = wredsum(sew);
            float inv = 1.f / (den + 1e-16f);
            float b0 = 0.f, b1 = 0.f;
            int e = s0;
            #pragma unroll 1
            for (; e + 1 < e1; e += 2) {
                float w0 = alp[e], w1v = alp[e + 1];
                int sA = srcp_s[e], sB = srcp_s[e + 1];
                a0 += w0 * vs[sA * 68 + lane];
                a1 += w0 * vs[sA * 68 + lane + 32];
                b0 += w1v * vs[sB * 68 + lane];
                b1 += w1v * vs[sB * 68 + lane + 32];
            }
            if (e < e1) {
                float w0 = alp[e]; int sA = srcp_s[e];
                a0 += w0 * vs[sA * 68 + lane];
                a1 += w0 * vs[sA * 68 + lane + 32];
            }
            a0 = (a0 + b0 + sew * we0) * inv;
            a1 = (a1 + b1 + sew * we1) * inv;
        }
        size_t r = base + i;
        float s0v = g_hin[r * KP1 + lane];
        float s1v = g_hin[r * KP1 + lane + 32];
        g_hin[r * KP1 + lane]      = fmaxf(a0 + s0v, 0.f);
        g_hin[r * KP1 + lane + 32] = fmaxf(a1 + s1v, 0.f);
    }
}

// ---------------- MLP (unchanged from R6; profiled as 4th launch) ----------------
#define MLP_SMEM_FLOATS (6656 + 16384 + 4096 + 64 + 64 + 256)
#define MLP_SMEM_BYTES  (MLP_SMEM_FLOATS * 4)

__global__ __launch_bounds__(256, 2) void mlp_kernel(
    const float* __restrict__ b1, const float* __restrict__ g1, const float* __restrict__ be1,
    const float* __restrict__ b2, const float* __restrict__ g2, const float* __restrict__ be2,
    const float* __restrict__ W3, const float* __restrict__ b3) {
    extern __shared__ float sm[];
    float* xs  = sm;                  // 32 pr x 104 k x 2
    float* hb  = xs + 6656;
    float* wp  = hb + 16384;
    float* mu  = wp + 4096;
    float* rsd = mu + 64;
    float* w3s = rsd + 64;
    ull* hbp = (ull*)hb;
    uint32_t wp_s32 = (uint32_t)__cvta_generic_to_shared(wp);
    int tid = threadIdx.x, lane = tid & 31, w = tid >> 5;
    int c4 = tid & 63, pbase = (tid >> 6) * 8;
    size_t row0 = (size_t)blockIdx.x * MROWS;

    {
        const float4* src4 = (const float4*)(g_hin + row0 * KP1);
        for (int i = tid; i < MROWS * 26; i += 256) {
            int r = i / 26, q = i - r * 26;
            float4 f = src4[i];
            float* d = xs + ((r >> 1) * KP1 + 4 * q) * 2 + (r & 1);
            d[0] = f.x; d[2] = f.y; d[4] = f.z; d[6] = f.w;
        }
    }
    w3s[tid] = W3[tid];
    __syncthreads();

    ull acc[4][8];
    gemm_panels<KP1>(g_W1U, xs, wp, wp_s32, ((const float4*)b1)[c4], acc, c4, pbase, tid);
    #pragma unroll
    for (int rp = 0; rp < 8; rp++)
        #pragma unroll
        for (int c = 0; c < 4; c++)
            hbp[(size_t)(pbase + rp) * HID + 4 * c4 + c] = acc[c][rp];
    __syncthreads();
    for (int r = w; r < MROWS; r += 8) {
        int pr = r >> 1, par = r & 1;
        float s = 0.f, s2 = 0.f;
        #pragma unroll
        for (int t = 0; t < 8; t++) {
            float v = hb[((size_t)pr * HID + lane + t * 32) * 2 + par];
            s += v; s2 += v * v;
        }
        s = wredsum(s); s2 = wredsum(s2);
        if (lane == 0) {
            float m = s * (1.f / HID);
            mu[r] = m;
            rsd[r] = rsqrtf(s2 * (1.f / HID) - m * m + 1e-5f);
        }
    }
    __syncthreads();
    {
        float4 gv = ((const float4*)g1)[c4], bev = ((const float4*)be1)[c4];
        float ga[4] = {gv.x, gv.y, gv.z, gv.w}, ba[4] = {bev.x, bev.y, bev.z, bev.w};
        #pragma unroll
        for (int rp = 0; rp < 8; rp++) {
            int pr = pbase + rp;
            float m0 = mu[2*pr], m1 = mu[2*pr+1], r0 = rsd[2*pr], r1 = rsd[2*pr+1];
            #pragma unroll
            for (int c = 0; c < 4; c++) {
                float lo, hi; up2(acc[c][rp], lo, hi);
                float h0 = (lo - m0) * r0 * ga[c] + ba[c];
                float h1 = (hi - m1) * r1 * ga[c] + ba[c];
                h0 = h0 > 0.f ? h0 : 0.01f * h0;
                h1 = h1 > 0.f ? h1 : 0.01f * h1;
                hbp[(size_t)pr * HID + 4 * c4 + c] = pk2(h0, h1);
            }
        }
    }
    __syncthreads();

    gemm_panels<HID>(g_W2U, hb, wp, wp_s32, ((const float4*)b2)[c4], acc, c4, pbase, tid);
    #pragma unroll
    for (int rp = 0; rp < 8; rp++)
        #pragma unroll
        for (int c = 0; c < 4; c++)
            hbp[(size_t)(pbase + rp) * HID + 4 * c4 + c] = acc[c][rp];
    __syncthreads();
    for (int r = w; r < MROWS; r += 8) {
        int pr = r >> 1, par = r & 1;
        float s = 0.f, s2 = 0.f;
        #pragma unroll
        for (int t = 0; t < 8; t++) {
            float v = hb[((size_t)pr * HID + lane + t * 32) * 2 + par];
            s += v; s2 += v * v;
        }
        s = wredsum(s); s2 = wredsum(s2);
        if (lane == 0) {
            float m = s * (1.f / HID);
            mu[r] = m;
            rsd[r] = rsqrtf(s2 * (1.f / HID) - m * m + 1e-5f);
        }
    }
    __syncthreads();
    {
        float4 gv = ((const float4*)g2)[c4], bev = ((const float4*)be2)[c4];
        float ga[4] = {gv.x, gv.y, gv.z, gv.w}, ba[4] = {bev.x, bev.y, bev.z, bev.w};
        #pragma unroll
        for (int rp = 0; rp < 8; rp++) {
            int pr = pbase + rp;
            float m0 = mu[2*pr], m1 = mu[2*pr+1], r0 = rsd[2*pr], r1 = rsd[2*pr+1];
            #pragma unroll
            for (int c = 0; c < 4; c++) {
                float lo, hi; up2(acc[c][rp], lo, hi);
                float w3c = w3s[4 * c4 + c];
                float h0 = (lo - m0) * r0 * ga[c] + ba[c];
                float h1 = (hi - m1) * r1 * ga[c] + ba[c];
                h0 = h0 > 0.f ? h0 : 0.01f * h0;
                h1 = h1 > 0.f ? h1 : 0.01f * h1;
                hbp[(size_t)pr * HID + 4 * c4 + c] = pk2(h0 * w3c, h1 * w3c);
            }
        }
    }
    __syncthreads();
    float b3v = b3[0];
    for (int r = w; r < MROWS; r += 8) {
        int pr = r >> 1, par = r & 1;
        float s = 0.f;
        #pragma unroll
        for (int t = 0; t < 8; t++)
            s += hb[((size_t)pr * HID + lane + t * 32) * 2 + par];
        s = wredsum(s);
        if (lane == 0) {
            float yv = s + b3v;
            g_conc[row0 + r] = (yv > 20.f) ? yv : log1pf(expf(yv));
        }
    }
}

// ---------------- final normalize per batch ----------------
__global__ __launch_bounds__(128) void final_kernel(float* __restrict__ out) {
    __shared__ float sb[4];
    int b = blockIdx.x, tid = threadIdx.x, lane = tid & 31, w = tid >> 5;
    float v = (tid < NNODE) ? g_conc[b * NNODE + tid] : 0.f;
    float s = v;
    #pragma unroll
    for (int o = 16; o; o >>= 1) s += __shfl_xor_sync(0xffffffffu, s, o);
    if (lane == 0) sb[w] = s;
    __syncthreads();
    float tt = sb[0] + sb[1] + sb[2] + sb[3];
    if (tid < NNODE) out[b * NNODE + tid] = v / (tt + 1e-20f);
}

// ---------------- launch ----------------
extern "C" void kernel_launch(void* const* d_in, const int* in_sizes, int n_in,
                              void* d_out, int out_size) {
    const float* state = (const float*)d_in[0];
    const float* pos   = (const float*)d_in[1];
    const float* ew    = (const float*)d_in[2];
    const float* Wq  = (const float*)d_in[3];  const float* bq  = (const float*)d_in[4];
    const float* Wk  = (const float*)d_in[5];  const float* bk  = (const float*)d_in[6];
    const float* Wv  = (const float*)d_in[7];  const float* bv  = (const float*)d_in[8];
    const float* We  = (const float*)d_in[9];
    const float* Wsk = (const float*)d_in[10]; const float* bsk = (const float*)d_in[11];
    const float* W1  = (const float*)d_in[12]; const float* b1  = (const float*)d_in[13];
    const float* g1  = (const float*)d_in[14]; const float* be1 = (const float*)d_in[15];
    const float* W2  = (const float*)d_in[16]; const float* b2  = (const float*)d_in[17];
    const float* g2  = (const float*)d_in[18]; const float* be2 = (const float*)d_in[19];
    const float* W3  = (const float*)d_in[20]; const float* b3  = (const float*)d_in[21];
    const int*   ei  = (const int*)d_in[22];
    float* out = (float*)d_out;

    cudaFuncSetAttribute(qkvs_kernel, cudaFuncAttributeMaxDynamicSharedMemorySize, QKVS_SMEM_BYTES);
    cudaFuncSetAttribute(edge_kernel, cudaFuncAttributeMaxDynamicSharedMemorySize, EDGE_SMEM_BYTES);
    cudaFuncSetAttribute(mlp_kernel,  cudaFuncAttributeMaxDynamicSharedMemorySize, MLP_SMEM_BYTES);

    prep_kernel<<<180, 256>>>(ei, ew, Wq, Wk, Wv, Wsk, W1, W2);        // 1
    qkvs_kernel<<<NROWS / MROWS, 256, QKVS_SMEM_BYTES>>>(state, pos, bq, bk, bv, bsk); // 2
    edge_kernel<<<BATCH, 256, EDGE_SMEM_BYTES>>>(state, pos, We);      // 3
    mlp_kernel<<<NROWS / MROWS, 256, MLP_SMEM_BYTES>>>(b1, g1, be1, b2, g2, be2, W3, b3); // 4 (profiled)
    final_kernel<<<BATCH, 128>>>(out);                                  // 5
}